// round 13
// baseline (speedup 1.0000x reference)
#include <cuda_runtime.h>
#include <math.h>
#include <stdint.h>

#define BL   4096
#define DD   1024
#define HH   16
#define OO   1024
#define FF   4096
#define LSEQ 1024
#define BSZN 4

// Arch-specific (sm_103a) feature gate: tcgen05 only compiles in the 'a' pass.
#if defined(__CUDA_ARCH__)
#  if defined(__CUDA_ARCH_FEAT_SM103_ALL) || defined(__CUDA_ARCH_FEAT_SM100_ALL) || \
      (defined(__CUDA_ARCH_SPECIFIC__) && (__CUDA_ARCH_SPECIFIC__ >= 1000))
#    define T5_OK 1
#  else
#    define T5_OK 0
#  endif
#else
#  define T5_OK 0
#endif

// ---------------- scratch (device globals; no allocation allowed) ----------
__device__ float g_xlnt[BL * DD];
__device__ float g_Bg  [BL * HH];
__device__ float g_hs  [BL * HH];
__device__ float g_y   [BL * DD];
__device__ float g_x3  [BL * DD];
__device__ float g_x3t [BL * DD];
__device__ float g_t   [BL * FF];

// ---------------- basic helpers --------------------------------------------
__device__ __forceinline__ float tf32r(float f) {
    uint32_t u;
    asm("cvt.rna.tf32.f32 %0, %1;" : "=r"(u) : "f"(f));
    return __uint_as_float(u);
}
__device__ __forceinline__ float sigm(float x) { return 1.f / (1.f + __expf(-x)); }

__device__ __forceinline__ void cp16(uint32_t s, const float* gp) {
    asm volatile("cp.async.cg.shared.global [%0], [%1], 16;" :: "r"(s), "l"(gp));
}
__device__ __forceinline__ void cp_commit() { asm volatile("cp.async.commit_group;"); }
template <int N>
__device__ __forceinline__ void cp_wait() { asm volatile("cp.async.wait_group %0;" :: "n"(N)); }

// legacy mma.sync (fallback path)
__device__ __forceinline__ void mma8(float* c, const uint32_t* a, const uint32_t* b) {
    asm volatile(
        "mma.sync.aligned.m16n8k8.row.col.f32.tf32.tf32.f32 "
        "{%0,%1,%2,%3},{%4,%5,%6,%7},{%8,%9},{%0,%1,%2,%3};"
        : "+f"(c[0]), "+f"(c[1]), "+f"(c[2]), "+f"(c[3])
        : "r"(a[0]), "r"(a[1]), "r"(a[2]), "r"(a[3]), "r"(b[0]), "r"(b[1]));
}

__device__ __forceinline__ bool elect1() {
    uint32_t p;
    asm volatile("{\n\t.reg .pred p;\n\telect.sync _|p, 0xFFFFFFFF;\n\tselp.b32 %0,1,0,p;\n\t}"
                 : "=r"(p));
    return p != 0;
}
__device__ __forceinline__ void mbar_init(uint32_t a, uint32_t cnt) {
    asm volatile("mbarrier.init.shared.b64 [%0], %1;" :: "r"(a), "r"(cnt) : "memory");
}
__device__ __forceinline__ void mbar_wait(uint32_t a, uint32_t parity) {
    asm volatile(
        "{\n\t.reg .pred P;\n"
        "WL%=:\n\t"
        "mbarrier.try_wait.parity.acquire.cta.shared::cta.b64 P, [%0], %1, 0x989680;\n\t"
        "@P bra WD%=;\n\t"
        "bra.uni WL%=;\n"
        "WD%=:\n\t}"
        :: "r"(a), "r"(parity) : "memory");
}

// ---------------- tcgen05 helpers ------------------------------------------
__device__ __forceinline__ void t5_alloc(uint32_t slot, uint32_t ncols) {
    asm volatile("tcgen05.alloc.cta_group::1.sync.aligned.shared::cta.b32 [%0], %1;"
                 :: "r"(slot), "r"(ncols) : "memory");
}
__device__ __forceinline__ void t5_relinquish() {
    asm volatile("tcgen05.relinquish_alloc_permit.cta_group::1.sync.aligned;");
}
__device__ __forceinline__ void t5_dealloc(uint32_t base, uint32_t ncols) {
    asm volatile("tcgen05.dealloc.cta_group::1.sync.aligned.b32 %0, %1;"
                 :: "r"(base), "r"(ncols));
}
__device__ __forceinline__ void t5_commit(uint32_t mbar) {
    asm volatile("tcgen05.commit.cta_group::1.mbarrier::arrive::one.shared::cluster.b64 [%0];"
                 :: "r"(mbar) : "memory");
}
__device__ __forceinline__ void t5_wait_ld() {
    asm volatile("tcgen05.wait::ld.sync.aligned;" ::: "memory");
}
__device__ __forceinline__ void t5_fence_after() {
    asm volatile("tcgen05.fence::after_thread_sync;" ::: "memory");
}
__device__ __forceinline__ void t5_fence_before() {
    asm volatile("tcgen05.fence::before_thread_sync;" ::: "memory");
}
__device__ __forceinline__ void fence_proxy_async_s() {
    asm volatile("fence.proxy.async.shared::cta;" ::: "memory");
}

#define IDESC_TF32 ((1u << 4) | (2u << 7) | (2u << 10) | ((128u / 8) << 17) | ((128u / 16) << 24))

__device__ __forceinline__ uint64_t mkdesc(uint32_t addr) {
    return ((uint64_t)2 << 61) | ((uint64_t)1 << 46) | ((uint64_t)64 << 32)
         | ((uint64_t)1 << 16) | ((addr >> 4) & 0x3FFF);
}
__device__ __forceinline__ void mma_tf32(uint32_t d, uint64_t a, uint64_t b, bool en) {
    uint32_t e = en ? 1u : 0u;
    asm volatile(
        "{\n\t.reg .pred p;\n\t"
        "setp.ne.u32 p, %4, 0;\n\t"
        "tcgen05.mma.cta_group::1.kind::tf32 [%0], %1, %2, %3, {%5, %5, %5, %5}, p;\n\t}"
        :: "r"(d), "l"(a), "l"(b), "r"(IDESC_TF32), "r"(e), "r"(0u) : "memory");
}
__device__ __forceinline__ void ldtm_x16(uint32_t* r, uint32_t a) {
    asm volatile(
        "tcgen05.ld.sync.aligned.32x32b.x16.b32 "
        "{%0,%1,%2,%3,%4,%5,%6,%7,%8,%9,%10,%11,%12,%13,%14,%15}, [%16];"
        : "=r"(r[0]),  "=r"(r[1]),  "=r"(r[2]),  "=r"(r[3]),
          "=r"(r[4]),  "=r"(r[5]),  "=r"(r[6]),  "=r"(r[7]),
          "=r"(r[8]),  "=r"(r[9]),  "=r"(r[10]), "=r"(r[11]),
          "=r"(r[12]), "=r"(r[13]), "=r"(r[14]), "=r"(r[15])
        : "r"(a));
}
__device__ __forceinline__ void ldtm_x32(uint32_t* r, uint32_t a) {
    asm volatile(
        "tcgen05.ld.sync.aligned.32x32b.x32.b32 "
        "{%0,%1,%2,%3,%4,%5,%6,%7,%8,%9,%10,%11,%12,%13,%14,%15,"
        "%16,%17,%18,%19,%20,%21,%22,%23,%24,%25,%26,%27,%28,%29,%30,%31}, [%32];"
        : "=r"(r[0]),  "=r"(r[1]),  "=r"(r[2]),  "=r"(r[3]),
          "=r"(r[4]),  "=r"(r[5]),  "=r"(r[6]),  "=r"(r[7]),
          "=r"(r[8]),  "=r"(r[9]),  "=r"(r[10]), "=r"(r[11]),
          "=r"(r[12]), "=r"(r[13]), "=r"(r[14]), "=r"(r[15]),
          "=r"(r[16]), "=r"(r[17]), "=r"(r[18]), "=r"(r[19]),
          "=r"(r[20]), "=r"(r[21]), "=r"(r[22]), "=r"(r[23]),
          "=r"(r[24]), "=r"(r[25]), "=r"(r[26]), "=r"(r[27]),
          "=r"(r[28]), "=r"(r[29]), "=r"(r[30]), "=r"(r[31])
        : "r"(a));
}

// ---------------- fused LN1 + B-projection ----------------------------------
__global__ __launch_bounds__(256) void lnprojB_kernel(
    const float* __restrict__ bv,
    const float* __restrict__ g1, const float* __restrict__ be1,
    const float* __restrict__ Wb, const float* __restrict__ bb,
    const float* __restrict__ Wbg, const float* __restrict__ bbg)
{
    int tid = threadIdx.x, warp = tid >> 5, lane = tid & 31;
#pragma unroll 1
    for (int rr = 0; rr < 4; ++rr) {
        int row = blockIdx.x * 32 + warp * 4 + rr;
        const float4* x4 = (const float4*)(bv + (size_t)row * DD);
        float4 xv[8];
        float s = 0.f, s2 = 0.f;
#pragma unroll
        for (int j = 0; j < 8; ++j) {
            xv[j] = x4[lane + 32 * j];
            s  += xv[j].x + xv[j].y + xv[j].z + xv[j].w;
            s2 += xv[j].x * xv[j].x + xv[j].y * xv[j].y
                + xv[j].z * xv[j].z + xv[j].w * xv[j].w;
        }
#pragma unroll
        for (int o = 16; o > 0; o >>= 1) {
            s  += __shfl_xor_sync(0xffffffffu, s,  o);
            s2 += __shfl_xor_sync(0xffffffffu, s2, o);
        }
        float mean = s * (1.0f / DD);
        float rstd = rsqrtf(s2 * (1.0f / DD) - mean * mean + 1e-5f);
        float4* xt4 = (float4*)(g_xlnt + (size_t)row * DD);
#pragma unroll
        for (int j = 0; j < 8; ++j) {
            float4 g4 = __ldg(&((const float4*)g1)[lane + 32 * j]);
            float4 b4 = __ldg(&((const float4*)be1)[lane + 32 * j]);
            xv[j].x = (xv[j].x - mean) * rstd * g4.x + b4.x;
            xv[j].y = (xv[j].y - mean) * rstd * g4.y + b4.y;
            xv[j].z = (xv[j].z - mean) * rstd * g4.z + b4.z;
            xv[j].w = (xv[j].w - mean) * rstd * g4.w + b4.w;
            float4 ot;
            ot.x = tf32r(xv[j].x); ot.y = tf32r(xv[j].y);
            ot.z = tf32r(xv[j].z); ot.w = tf32r(xv[j].w);
            xt4[lane + 32 * j] = ot;
        }
#pragma unroll 1
        for (int h = 0; h < HH; ++h) {
            const float4* wb4 = (const float4*)(Wb  + (size_t)h * DD);
            const float4* wg4 = (const float4*)(Wbg + (size_t)h * DD);
            float sb = 0.f, sg = 0.f;
#pragma unroll
            for (int j = 0; j < 8; ++j) {
                float4 w0 = __ldg(&wb4[lane + 32 * j]);
                float4 w1 = __ldg(&wg4[lane + 32 * j]);
                sb += xv[j].x * w0.x + xv[j].y * w0.y + xv[j].z * w0.z + xv[j].w * w0.w;
                sg += xv[j].x * w1.x + xv[j].y * w1.y + xv[j].z * w1.z + xv[j].w * w1.w;
            }
#pragma unroll
            for (int o = 16; o > 0; o >>= 1) {
                sb += __shfl_down_sync(0xffffffffu, sb, o);
                sg += __shfl_down_sync(0xffffffffu, sg, o);
            }
            if (lane == 0) {
                float bval = sb + bb[h];
                float gval = sg + bbg[h];
                g_Bg[(size_t)row * HH + h] = bval * (1.f / (1.f + expf(-gval)));
            }
        }
    }
}

// ---------------- LayerNorm (LN2) --------------------------------------------
__global__ void ln_kernel(const float* __restrict__ gw,
                          const float* __restrict__ bw) {
    int row = blockIdx.x;
    int tid = threadIdx.x;
    const float* x = g_y + (size_t)row * DD;
    float* dst  = g_x3  + (size_t)row * DD;
    float* dstt = g_x3t + (size_t)row * DD;

    float4 v = ((const float4*)x)[tid];
    float s  = v.x + v.y + v.z + v.w;
    float s2 = v.x * v.x + v.y * v.y + v.z * v.z + v.w * v.w;
#pragma unroll
    for (int o = 16; o > 0; o >>= 1) {
        s  += __shfl_down_sync(0xffffffffu, s,  o);
        s2 += __shfl_down_sync(0xffffffffu, s2, o);
    }
    __shared__ float rs[8], rs2[8], stats[2];
    int warp = tid >> 5, lane = tid & 31;
    if (lane == 0) { rs[warp] = s; rs2[warp] = s2; }
    __syncthreads();
    if (tid == 0) {
        float a = 0.f, b = 0.f;
#pragma unroll
        for (int i = 0; i < 8; i++) { a += rs[i]; b += rs2[i]; }
        float mean = a * (1.0f / DD);
        float var  = b * (1.0f / DD) - mean * mean;
        stats[0] = mean; stats[1] = rsqrtf(var + 1e-5f);
    }
    __syncthreads();
    float mean = stats[0], rstd = stats[1];
    float4 g4 = ((const float4*)gw)[tid];
    float4 b4 = ((const float4*)bw)[tid];
    float4 o;
    o.x = (v.x - mean) * rstd * g4.x + b4.x;
    o.y = (v.y - mean) * rstd * g4.y + b4.y;
    o.z = (v.z - mean) * rstd * g4.z + b4.z;
    o.w = (v.w - mean) * rstd * g4.w + b4.w;
    ((float4*)dst)[tid] = o;
    float4 ot;
    ot.x = tf32r(o.x); ot.y = tf32r(o.y); ot.z = tf32r(o.z); ot.w = tf32r(o.w);
    ((float4*)dstt)[tid] = ot;
}

// ---------------- selective scan ----------------------------------------------
__global__ void scan_kernel(const float* __restrict__ h0,
                            const float* __restrict__ A,
                            float* __restrict__ lasth, int write_last) {
    int tt = threadIdx.x;
    if (tt >= BSZN * HH) return;
    int b = tt / HH, h = tt % HH;
    float dA = expf(A[h]);
    float hc = h0[b * HH + h];
    const float* bp = g_Bg + (size_t)b * LSEQ * HH + h;
    float* hp = g_hs + (size_t)b * LSEQ * HH + h;
#pragma unroll 4
    for (int l = 0; l < LSEQ; l++) {
        hc = dA * hc + bp[(size_t)l * HH];
        hp[(size_t)l * HH] = hc;
    }
    if (write_last) lasth[b * HH + h] = hc;
}

// ---------------- fallback mma.sync GEMM pass -------------------------------
#define TSTR 36
#define STAGE_F (128 * TSTR)

template <bool DUAL>
__device__ __forceinline__ void fb_gemm_pass(
    const float* __restrict__ W0, const float* __restrict__ W1p,
    const float* sX, const float* sWc, const float* sWg,
    uint32_t sXu, uint32_t sWcu, uint32_t sWgu,
    int tid, int g, int t, int wm, int wn, int mBase, int nBase,
    float (*accC)[4][4], float (*accG)[4][4])
{
    auto issue = [&](int kc, int st) {
        int k0 = kc * 32;
#pragma unroll
        for (int i = 0; i < 4; i++) {
            int j = tid + i * 256; int row = j >> 3; int c = (j & 7) * 4;
            cp16(sXu + (uint32_t)(((st * 128 + row) * TSTR) + c) * 4,
                 &g_xlnt[(size_t)(mBase + row) * DD + k0 + c]);
        }
#pragma unroll
        for (int i = 0; i < 4; i++) {
            int j = tid + i * 256; int row = j >> 3; int c = (j & 7) * 4;
            cp16(sWcu + (uint32_t)(((st * 128 + row) * TSTR) + c) * 4,
                 &W0[(size_t)(nBase + row) * DD + k0 + c]);
        }
        if (DUAL) {
#pragma unroll
            for (int i = 0; i < 4; i++) {
                int j = tid + i * 256; int row = j >> 3; int c = (j & 7) * 4;
                cp16(sWgu + (uint32_t)(((st * 128 + row) * TSTR) + c) * 4,
                     &W1p[(size_t)(nBase + row) * DD + k0 + c]);
            }
        }
        cp_commit();
    };

    issue(0, 0);
#pragma unroll 1
    for (int kc = 0; kc < 32; ++kc) {
        cp_wait<0>();
        __syncthreads();
        if (kc + 1 < 32) issue(kc + 1, (kc + 1) & 1);
        const float* xb  = sX  + (kc & 1) * STAGE_F;
        const float* wcb = sWc + (kc & 1) * STAGE_F;
        const float* wgb = sWg + (kc & 1) * STAGE_F;
#pragma unroll
        for (int kk = 0; kk < 4; ++kk) {
            int ks = kk * 8;
            uint32_t a[4][4];
#pragma unroll
            for (int mt = 0; mt < 4; ++mt) {
                int r = wm + mt * 16 + g;
                a[mt][0] = __float_as_uint(xb[r * TSTR + ks + t]);
                a[mt][1] = __float_as_uint(xb[(r + 8) * TSTR + ks + t]);
                a[mt][2] = __float_as_uint(xb[r * TSTR + ks + t + 4]);
                a[mt][3] = __float_as_uint(xb[(r + 8) * TSTR + ks + t + 4]);
            }
            uint32_t bC[4][2], bG[4][2];
#pragma unroll
            for (int nt = 0; nt < 4; ++nt) {
                int cn = wn + nt * 8 + g;
                bC[nt][0] = __float_as_uint(wcb[cn * TSTR + ks + t]);
                bC[nt][1] = __float_as_uint(wcb[cn * TSTR + ks + t + 4]);
                if (DUAL) {
                    bG[nt][0] = __float_as_uint(wgb[cn * TSTR + ks + t]);
                    bG[nt][1] = __float_as_uint(wgb[cn * TSTR + ks + t + 4]);
                }
            }
#pragma unroll
            for (int mt = 0; mt < 4; ++mt)
#pragma unroll
                for (int nt = 0; nt < 4; ++nt) {
                    mma8(accC[mt][nt], a[mt], bC[nt]);
                    if (DUAL) mma8(accG[mt][nt], a[mt], bG[nt]);
                }
        }
        __syncthreads();
    }
}

// ============================================================================
// Fused SSM kernel — flattened 544-chunk pipeline (tcgen05), raw fp32 weights.
// ============================================================================
#define F_HS   2048
#define F_ST   19456
#define F_STSZ 65536
#define FUSED_SMEM (19456 + 3 * 65536 + 1024)
#define NCH_TOT (17 * 32)

__global__ __launch_bounds__(256, 1)
void fused_ssm_t5(const float* __restrict__ Wc, const float* __restrict__ Wcg,
                  const float* __restrict__ Wd,
                  const float* __restrict__ bc, const float* __restrict__ bcg,
                  const float* __restrict__ bd, const float* __restrict__ bv)
{
    extern __shared__ char smraw[];
#if T5_OK
    uint32_t sraw = (uint32_t)__cvta_generic_to_shared(smraw);
    uint32_t sbase = (sraw + 1023) & ~1023u;
    float* smf = (float*)(smraw + (sbase - sraw));
    float* sBC = smf + 32;
    float* sBG = smf + 160;
    float* sHS = smf + F_HS / 4;

    const int tid = threadIdx.x;
    const int wid = tid >> 5, lane = tid & 31;
    const int sp = wid & 3, ch = wid >> 2;
    const int mBase = blockIdx.y * 256;
    const int nBase = blockIdx.x * 128;

    if (wid == 0) t5_alloc(sbase, 512);
    if (tid == 0) {
        mbar_init(sbase + 8, 1);
        mbar_init(sbase + 16, 1);
        mbar_init(sbase + 24, 1);
    }
    for (int i = tid; i < 256 * 16; i += 256) {
        int r = i >> 4, h = i & 15;
        sHS[r * 17 + h] = g_hs[(size_t)(mBase + r) * HH + h];
    }
    __syncthreads();
    uint32_t tmem;
    asm volatile("ld.shared.b32 %0, [%1];" : "=r"(tmem) : "r"(sbase));
    if (wid == 0) t5_relinquish();

    float ssm[128];
#pragma unroll
    for (int i = 0; i < 128; i++) ssm[i] = 0.f;

    auto fill = [&](int cg) {
        int head = cg >> 5, kc = cg & 31, st = cg % 3;
        bool dual = (head < 16);
        const float* Wc_h = dual ? (Wc + (size_t)head * OO * DD) : Wd;
        const float* Wg_h = Wcg + (size_t)(dual ? head : 0) * OO * DD;
        uint32_t sa = sbase + F_ST + st * F_STSZ;
        int k0 = kc * 32;
#pragma unroll
        for (int i = 0; i < 8; i++) {
            int id = tid + i * 256;
            int row = id >> 3, c = (id & 7) * 16;
            uint32_t off = (uint32_t)(row * 128 + c);
            uint32_t sw = off ^ ((off >> 3) & 0x70);
            cp16(sa + sw, &g_xlnt[(size_t)(mBase + row) * DD + k0 + (c >> 2)]);
        }
#pragma unroll
        for (int i = 0; i < 4; i++) {
            int id = tid + i * 256;
            int row = id >> 3, c = (id & 7) * 16;
            uint32_t off = (uint32_t)(row * 128 + c);
            uint32_t sw = off ^ ((off >> 3) & 0x70);
            cp16(sa + 32768 + sw, &Wc_h[(size_t)(nBase + row) * DD + k0 + (c >> 2)]);
            if (dual)
                cp16(sa + 49152 + sw, &Wg_h[(size_t)(nBase + row) * DD + k0 + (c >> 2)]);
        }
        cp_commit();
    };

    auto epilogue = [&](int h) {
        bool dual = (h < 16);
        if (tid < 128) {
            sBC[tid] = dual ? bc[h * OO + nBase + tid] : bd[nBase + tid];
        } else if (dual) {
            sBG[tid - 128] = bcg[h * OO + nBase + (tid - 128)];
        }
        __syncthreads();
        t5_fence_after();
#pragma unroll
        for (int s = 0; s < 2; ++s) {
            float hsv = 1.f;
            if (dual) hsv = sHS[(s * 128 + sp * 32 + lane) * 17 + h];
#pragma unroll
            for (int q = 0; q < 4; ++q) {
                uint32_t cb[16], gb[16];
                uint32_t ca = tmem + s * 128 + ch * 64 + q * 16;
                ldtm_x16(cb, ca);
                if (dual) ldtm_x16(gb, ca + 256);
                t5_wait_ld();
#pragma unroll
                for (int j = 0; j < 16; ++j) {
                    int col = ch * 64 + q * 16 + j;
                    float cc = __uint_as_float(cb[j]) + sBC[col];
                    if (dual) {
                        float gg = __uint_as_float(gb[j]) + sBG[col];
                        ssm[s * 64 + q * 16 + j] += hsv * cc * sigm(gg);
                    } else {
                        ssm[s * 64 + q * 16 + j] += cc;
                    }
                }
            }
        }
        t5_fence_before();
        __syncthreads();
    };

    fill(0);
    fill(1);
#pragma unroll 1
    for (int cg = 0; cg < NCH_TOT; ++cg) {
        int kc = cg & 31, head = cg >> 5, s = cg % 3;
        if (kc == 0 && head > 0) {
            mbar_wait(sbase + 8 + 8 * ((cg - 1) % 3), ((cg - 1) / 3) & 1);
            epilogue(head - 1);
        }
        if (cg < NCH_TOT - 1) cp_wait<1>(); else cp_wait<0>();
        fence_proxy_async_s();
        __syncthreads();
        if (wid == 0 && elect1()) {
            bool dual = (head < 16);
            uint32_t sa = sbase + F_ST + s * F_STSZ;
            uint64_t dA0 = mkdesc(sa), dA1 = mkdesc(sa + 16384);
            uint64_t dBc = mkdesc(sa + 32768), dBg = mkdesc(sa + 49152);
#pragma unroll
            for (int ks = 0; ks < 4; ++ks) {
                bool en = !(kc == 0 && ks == 0);
                uint64_t o = (uint64_t)(ks * 2);
                mma_tf32(tmem + 0,   dA0 + o, dBc + o, en);
                mma_tf32(tmem + 128, dA1 + o, dBc + o, en);
                if (dual) {
                    mma_tf32(tmem + 256, dA0 + o, dBg + o, en);
                    mma_tf32(tmem + 384, dA1 + o, dBg + o, en);
                }
            }
            t5_commit(sbase + 8 + 8 * s);
        }
        if (cg + 2 < NCH_TOT) {
            if (cg >= 1)
                mbar_wait(sbase + 8 + 8 * ((cg - 1) % 3), ((cg - 1) / 3) & 1);
            fill(cg + 2);
        }
    }
    mbar_wait(sbase + 8 + 8 * ((NCH_TOT - 1) % 3), ((NCH_TOT - 1) / 3) & 1);
    epilogue(16);

#pragma unroll
    for (int s = 0; s < 2; ++s) {
        int r = mBase + s * 128 + sp * 32 + lane;
        size_t ga = (size_t)r * DD + nBase + ch * 64;
#pragma unroll
        for (int q = 0; q < 16; ++q) {
            float4 b4 = *reinterpret_cast<const float4*>(&bv[ga + q * 4]);
            float4 o;
            o.x = b4.x + ssm[s * 64 + q * 4 + 0];
            o.y = b4.y + ssm[s * 64 + q * 4 + 1];
            o.z = b4.z + ssm[s * 64 + q * 4 + 2];
            o.w = b4.w + ssm[s * 64 + q * 4 + 3];
            *reinterpret_cast<float4*>(&g_y[ga + q * 4]) = o;
        }
    }

    __syncthreads();
    if (wid == 0) t5_dealloc(tmem, 512);
#else
    float* sm  = (float*)smraw;
    float* sX  = sm;
    float* sWc = sm + 2 * STAGE_F;
    float* sWg = sm + 4 * STAGE_F;
    float* sS  = sm + 6 * STAGE_F;
    float* sHS = sS + 128 * 136;

    const int tid = threadIdx.x;
    const int wid = tid >> 5, lane = tid & 31;
    const int g = lane >> 2, t = lane & 3;
    const int wm = (wid >> 2) * 64;
    const int wn = (wid & 3) * 32;
    const int nBase = blockIdx.x * 128;
    uint32_t sXu  = (uint32_t)__cvta_generic_to_shared(sX);
    uint32_t sWcu = (uint32_t)__cvta_generic_to_shared(sWc);
    uint32_t sWgu = (uint32_t)__cvta_generic_to_shared(sWg);

    for (int sub = 0; sub < 2; ++sub) {
        const int mBase = blockIdx.y * 256 + sub * 128;
        for (int i = tid; i < 128 * 136; i += 256) sS[i] = 0.f;
        for (int i = tid; i < 128 * 16; i += 256) {
            int r = i >> 4, h = i & 15;
            sHS[r * 17 + h] = g_hs[(size_t)(mBase + r) * HH + h];
        }
        __syncthreads();

        float accC[4][4][4], accG[4][4][4];
        for (int pass = 0; pass < HH; ++pass) {
#pragma unroll
            for (int mt = 0; mt < 4; ++mt)
#pragma unroll
                for (int nt = 0; nt < 4; ++nt)
#pragma unroll
                    for (int k = 0; k < 4; ++k) { accC[mt][nt][k] = 0.f; accG[mt][nt][k] = 0.f; }

            fb_gemm_pass<true>(Wc + (size_t)pass * OO * DD,
                               Wcg + (size_t)pass * OO * DD,
                               sX, sWc, sWg, sXu, sWcu, sWgu,
                               tid, g, t, wm, wn, mBase, nBase, accC, accG);

#pragma unroll
            for (int mt = 0; mt < 4; ++mt) {
                int r0 = wm + mt * 16 + g;
                float hs0 = sHS[r0 * 17 + pass];
                float hs1 = sHS[(r0 + 8) * 17 + pass];
#pragma unroll
                for (int nt = 0; nt < 4; ++nt) {
                    int c0 = wn + nt * 8 + 2 * t;
                    int cg0 = nBase + c0;
                    float bc0 = __ldg(&bc[pass * OO + cg0]);
                    float bc1 = __ldg(&bc[pass * OO + cg0 + 1]);
                    float bg0 = __ldg(&bcg[pass * OO + cg0]);
                    float bg1 = __ldg(&bcg[pass * OO + cg0 + 1]);
                    float* s0 = &sS[r0 * 136 + c0];
                    float* s1 = &sS[(r0 + 8) * 136 + c0];
                    s0[0] += hs0 * (accC[mt][nt][0] + bc0) * sigm(accG[mt][nt][0] + bg0);
                    s0[1] += hs0 * (accC[mt][nt][1] + bc1) * sigm(accG[mt][nt][1] + bg1);
                    s1[0] += hs1 * (accC[mt][nt][2] + bc0) * sigm(accG[mt][nt][2] + bg0);
                    s1[1] += hs1 * (accC[mt][nt][3] + bc1) * sigm(accG[mt][nt][3] + bg1);
                }
            }
        }

#pragma unroll
        for (int mt = 0; mt < 4; ++mt)
#pragma unroll
            for (int nt = 0; nt < 4; ++nt)
#pragma unroll
                for (int k = 0; k < 4; ++k) accC[mt][nt][k] = 0.f;

        fb_gemm_pass<false>(Wd, Wd, sX, sWc, sWg, sXu, sWcu, sWgu,
                            tid, g, t, wm, wn, mBase, nBase, accC, accG);

#pragma unroll
        for (int mt = 0; mt < 4; ++mt) {
            int r0 = wm + mt * 16 + g;
#pragma unroll
            for (int nt = 0; nt < 4; ++nt) {
                int c0 = wn + nt * 8 + 2 * t;
                int cg0 = nBase + c0;
                float bd0 = __ldg(&bd[cg0]);
                float bd1 = __ldg(&bd[cg0 + 1]);
                float* s0 = &sS[r0 * 136 + c0];
                float* s1 = &sS[(r0 + 8) * 136 + c0];
                s0[0] += accC[mt][nt][0] + bd0;
                s0[1] += accC[mt][nt][1] + bd1;
                s1[0] += accC[mt][nt][2] + bd0;
                s1[1] += accC[mt][nt][3] + bd1;
            }
        }

#pragma unroll
        for (int mt = 0; mt < 4; ++mt) {
            int r0 = wm + mt * 16 + g;
#pragma unroll
            for (int nt = 0; nt < 4; ++nt) {
                int c0 = wn + nt * 8 + 2 * t;
#pragma unroll
                for (int half = 0; half < 2; ++half) {
                    int r = r0 + 8 * half;
                    size_t gaddr = (size_t)(mBase + r) * DD + nBase + c0;
                    float2 bvv = *reinterpret_cast<const float2*>(&bv[gaddr]);
                    float2 sv  = *reinterpret_cast<float2*>(&sS[r * 136 + c0]);
                    float2 o; o.x = bvv.x + sv.x; o.y = bvv.y + sv.y;
                    *reinterpret_cast<float2*>(&g_y[gaddr]) = o;
                }
            }
        }
        __syncthreads();
    }
#endif
}

// ============================================================================
// FFN1: M=256 x N=256 per CTA. out = tf32r(gelu(A@B.T+b))
// ============================================================================
#define FFN1_SMEM (2048 + 3 * 65536 + 1024)

__global__ __launch_bounds__(256, 1)
void ffn1_t5(const float* __restrict__ Amat, const float* __restrict__ Bmat,
             const float* __restrict__ bias, float* __restrict__ outp)
{
    extern __shared__ char smraw[];
#if T5_OK
    uint32_t sraw = (uint32_t)__cvta_generic_to_shared(smraw);
    uint32_t sbase = (sraw + 1023) & ~1023u;
    float* smf = (float*)(smraw + (sbase - sraw));
    float* sB = smf + 32;

    const int tid = threadIdx.x;
    const int wid = tid >> 5, lane = tid & 31;
    const int sp = wid & 3, ch = wid >> 2;
    const int mBase = blockIdx.y * 256;
    const int nBase = blockIdx.x * 256;
    const int NC = DD / 32;

    if (wid == 0) t5_alloc(sbase, 512);
    if (tid == 0) {
        mbar_init(sbase + 8, 1);
        mbar_init(sbase + 16, 1);
        mbar_init(sbase + 24, 1);
    }
    sB[tid] = bias[nBase + tid];
    __syncthreads();
    uint32_t tmem;
    asm volatile("ld.shared.b32 %0, [%1];" : "=r"(tmem) : "r"(sbase));
    if (wid == 0) t5_relinquish();

    uint32_t wcnt[3] = {0, 0, 0};

    auto fill = [&](int kc, int st) {
        uint32_t sa = sbase + 2048 + st * 65536;
        int k0 = kc * 32;
#pragma unroll
        for (int i = 0; i < 8; i++) {
            int id = tid + i * 256;
            int row = id >> 3, c = (id & 7) * 16;
            uint32_t off = (uint32_t)(row * 128 + c);
            uint32_t sw = off ^ ((off >> 3) & 0x70);
            cp16(sa + sw, &Amat[(size_t)(mBase + row) * DD + k0 + (c >> 2)]);
        }
#pragma unroll
        for (int i = 0; i < 8; i++) {
            int id = tid + i * 256;
            int row = id >> 3, c = (id & 7) * 16;
            uint32_t off = (uint32_t)(row * 128 + c);
            uint32_t sw = off ^ ((off >> 3) & 0x70);
            cp16(sa + 32768 + sw, &Bmat[(size_t)(nBase + row) * DD + k0 + (c >> 2)]);
        }
        cp_commit();
    };

    fill(0, 0);
    fill(1, 1);
#pragma unroll 1
    for (int kc = 0; kc < NC; ++kc) {
        int s = kc % 3;
        if (kc < NC - 1) cp_wait<1>(); else cp_wait<0>();
        fence_proxy_async_s();
        __syncthreads();
        if (wid == 0 && elect1()) {
            uint32_t sa = sbase + 2048 + s * 65536;
            uint64_t dA0 = mkdesc(sa), dA1 = mkdesc(sa + 16384);
            uint64_t dB0 = mkdesc(sa + 32768), dB1 = mkdesc(sa + 49152);
#pragma unroll
            for (int ks = 0; ks < 4; ++ks) {
                bool en = !(kc == 0 && ks == 0);
                uint64_t o = (uint64_t)(ks * 2);
                mma_tf32(tmem + 0,   dA0 + o, dB0 + o, en);
                mma_tf32(tmem + 128, dA0 + o, dB1 + o, en);
                mma_tf32(tmem + 256, dA1 + o, dB0 + o, en);
                mma_tf32(tmem + 384, dA1 + o, dB1 + o, en);
            }
            t5_commit(sbase + 8 + 8 * s);
        }
        if (kc + 2 < NC) {
            if (kc >= 1) {
                int ps = (kc - 1) % 3;
                mbar_wait(sbase + 8 + 8 * ps, wcnt[ps] & 1);
                wcnt[ps]++;
            }
            fill(kc + 2, (kc + 2) % 3);
        }
    }
#pragma unroll
    for (int c = NC - 3; c < NC; ++c) {
        int s = c % 3;
        mbar_wait(sbase + 8 + 8 * s, wcnt[s] & 1);
        wcnt[s]++;
    }

    __syncthreads();
    t5_fence_after();
#pragma unroll
    for (int ms = 0; ms < 2; ++ms) {
        int r = mBase + ms * 128 + sp * 32 + lane;
#pragma unroll
        for (int ns = 0; ns < 2; ++ns) {
#pragma unroll
            for (int half = 0; half < 2; ++half) {
                uint32_t cb[32];
                ldtm_x32(cb, tmem + ms * 256 + ns * 128 + ch * 64 + half * 32);
                t5_wait_ld();
                int colb = ns * 128 + ch * 64 + half * 32;
                size_t ga = (size_t)r * FF + nBase + colb;
#pragma unroll
                for (int q = 0; q < 8; ++q) {
                    float4 o;
                    float v0 = __uint_as_float(cb[q * 4 + 0]) + sB[colb + q * 4 + 0];
                    float v1 = __uint_as_float(cb[q * 4 + 1]) + sB[colb + q * 4 + 1];
                    float v2 = __uint_as_float(cb[q * 4 + 2]) + sB[colb + q * 4 + 2];
                    float v3 = __uint_as_float(cb[q * 4 + 3]) + sB[colb + q * 4 + 3];
                    o.x = tf32r(0.5f * v0 * (1.0f + erff(v0 * 0.70710678118654752f)));
                    o.y = tf32r(0.5f * v1 * (1.0f + erff(v1 * 0.70710678118654752f)));
                    o.z = tf32r(0.5f * v2 * (1.0f + erff(v2 * 0.70710678118654752f)));
                    o.w = tf32r(0.5f * v3 * (1.0f + erff(v3 * 0.70710678118654752f)));
                    *reinterpret_cast<float4*>(&outp[ga + q * 4]) = o;
                }
            }
        }
    }
    t5_fence_before();
    __syncthreads();
    if (wid == 0) t5_dealloc(tmem, 512);
#else
    float* sm = (float*)smraw;
    float* sX = sm;
    float* sW = sm + 2 * STAGE_F;
    const int tid = threadIdx.x;
    const int wid = tid >> 5, lane = tid & 31;
    const int g = lane >> 2, t = lane & 3;
    const int wm = (wid >> 2) * 64;
    const int wn = (wid & 3) * 32;
    uint32_t sXu = (uint32_t)__cvta_generic_to_shared(sX);
    uint32_t sWu = (uint32_t)__cvta_generic_to_shared(sW);

    for (int ns = 0; ns < 2; ++ns) {
        const int nBase = blockIdx.x * 256 + ns * 128;
        for (int sub = 0; sub < 2; ++sub) {
            const int mBase = blockIdx.y * 256 + sub * 128;
            float acc[4][4][4];
#pragma unroll
            for (int mt = 0; mt < 4; ++mt)
#pragma unroll
                for (int nt = 0; nt < 4; ++nt)
#pragma unroll
                    for (int k = 0; k < 4; ++k) acc[mt][nt][k] = 0.f;

            auto issue = [&](int kc, int st) {
                int k0 = kc * 32;
#pragma unroll
                for (int i = 0; i < 4; i++) {
                    int j = tid + i * 256; int row = j >> 3; int c = (j & 7) * 4;
                    cp16(sXu + (uint32_t)(((st * 128 + row) * TSTR) + c) * 4,
                         &Amat[(size_t)(mBase + row) * DD + k0 + c]);
                }
#pragma unroll
                for (int i = 0; i < 4; i++) {
                    int j = tid + i * 256; int row = j >> 3; int c = (j & 7) * 4;
                    cp16(sWu + (uint32_t)(((st * 128 + row) * TSTR) + c) * 4,
                         &Bmat[(size_t)(nBase + row) * DD + k0 + c]);
                }
                cp_commit();
            };

            issue(0, 0);
#pragma unroll 1
            for (int kc = 0; kc < 32; ++kc) {
                cp_wait<0>();
                __syncthreads();
                if (kc + 1 < 32) issue(kc + 1, (kc + 1) & 1);
                const float* xb = sX + (kc & 1) * STAGE_F;
                const float* wb = sW + (kc & 1) * STAGE_F;
#pragma unroll
                for (int kk = 0; kk < 4; ++kk) {
                    int ks = kk * 8;
                    uint32_t a[4][4], b[4][2];
#pragma unroll
                    for (int mt = 0; mt < 4; ++mt) {
                        int r = wm + mt * 16 + g;
                        a[mt][0] = __float_as_uint(xb[r * TSTR + ks + t]);
                        a[mt][1] = __float_as_uint(xb[(r + 8) * TSTR + ks + t]);
                        a[mt][2] = __float_as_uint(xb[r * TSTR + ks + t + 4]);
                        a[mt][3] = __float_as_uint(xb[(r + 8) * TSTR + ks + t + 4]);
                    }
#pragma unroll
                    for (int nt = 0; nt < 4; ++nt) {
                        int cn = wn + nt * 8 + g;
                        b[nt][0] = __float_as_uint(wb[cn * TSTR + ks + t]);
                        b[nt][1] = __float_as_uint(wb[cn * TSTR + ks + t + 4]);
                    }
#pragma unroll
                    for (int mt = 0; mt < 4; ++mt)
#pragma unroll
                        for (int nt = 0; nt < 4; ++nt) mma8(acc[mt][nt], a[mt], b[nt]);
                }
                __syncthreads();
            }

#pragma unroll
            for (int mt = 0; mt < 4; ++mt) {
                int r0 = wm + mt * 16 + g;
#pragma unroll
                for (int nt = 0; nt < 4; ++nt) {
                    int c0 = wn + nt * 8 + 2 * t;
                    int nc = nBase + c0;
                    float bb0 = __ldg(&bias[nc]), bb1 = __ldg(&bias[nc + 1]);
#pragma unroll
                    for (int half = 0; half < 2; ++half) {
                        int r = r0 + 8 * half;
                        size_t ga = (size_t)(mBase + r) * FF + nc;
                        float v0 = acc[mt][nt][half * 2 + 0] + bb0;
                        float v1 = acc[mt][nt][half * 2 + 1] + bb1;
                        v0 = 0.5f * v0 * (1.0f + erff(v0 * 0.70710678118654752f));
                        v1 = 0.5f * v1 * (1.0f + erff(v1 * 0.70710678118654752f));
                        float2 o; o.x = tf32r(v0); o.y = tf32r(v1);
                        *reinterpret_cast<float2*>(&outp[ga]) = o;
                    }
                }
            }
            __syncthreads();
        }
    }
#endif
}

// ============================================================================
// FFN2: M=128 x N=128, K=4096, 2 CTAs/SM. outp = res + A @ B.T + bias
// smem: +0 tmemptr, mbar[3]@8/16/24, sB@128; stages @2048: 3 x 32768 (A16K,B16K)
// ============================================================================
#define FFN2_SMEM (2048 + 3 * 32768 + 1024)   // 101376

__global__ __launch_bounds__(256, 2)
void ffn2_t5(const float* __restrict__ Amat, const float* __restrict__ Bmat,
             const float* __restrict__ bias, const float* __restrict__ res,
             float* __restrict__ outp)
{
    extern __shared__ char smraw[];
#if T5_OK
    uint32_t sraw = (uint32_t)__cvta_generic_to_shared(smraw);
    uint32_t sbase = (sraw + 1023) & ~1023u;
    float* smf = (float*)(smraw + (sbase - sraw));
    float* sB = smf + 32;

    const int tid = threadIdx.x;
    const int wid = tid >> 5, lane = tid & 31;
    const int sp = wid & 3, ch = wid >> 2;
    const int mBase = blockIdx.y * 128;
    const int nBase = blockIdx.x * 128;
    const int NC = FF / 32;   // 128

    if (wid == 0) t5_alloc(sbase, 128);
    if (tid == 0) {
        mbar_init(sbase + 8, 1);
        mbar_init(sbase + 16, 1);
        mbar_init(sbase + 24, 1);
    }
    if (tid < 128) sB[tid] = bias[nBase + tid];
    __syncthreads();
    uint32_t tmem;
    asm volatile("ld.shared.b32 %0, [%1];" : "=r"(tmem) : "r"(sbase));
    if (wid == 0) t5_relinquish();

    uint32_t wcnt[3] = {0, 0, 0};

    auto fill = [&](int kc, int st) {
        uint32_t sa = sbase + 2048 + st * 32768;
        int k0 = kc * 32;
#pragma unroll
        for (int i = 0; i < 4; i++) {
            int id = tid + i * 256;
            int row = id >> 3, c = (id & 7) * 16;
            uint32_t off = (uint32_t)(row * 128 + c);
            uint32_t sw = off ^ ((off >> 3) & 0x70);
            cp16(sa + sw, &Amat[(size_t)(mBase + row) * FF + k0 + (c >> 2)]);
            cp16(sa + 16384 + sw, &Bmat[(size_t)(nBase + row) * FF + k0 + (c >> 2)]);
        }
        cp_commit();
    };

    fill(0, 0);
    fill(1, 1);
#pragma unroll 1
    for (int kc = 0; kc < NC; ++kc) {
        int s = kc % 3;
        if (kc < NC - 1) cp_wait<1>(); else cp_wait<0>();
        fence_proxy_async_s();
        __syncthreads();
        if (wid == 0 && elect1()) {
            uint32_t sa = sbase + 2048 + s * 32768;
            uint64_t dA = mkdesc(sa), dB = mkdesc(sa + 16384);
#pragma unroll
            for (int ks = 0; ks < 4; ++ks) {
                bool en = !(kc == 0 && ks == 0);
                uint64_t o = (uint64_t)(ks * 2);
                mma_tf32(tmem, dA + o, dB + o, en);
            }
            t5_commit(sbase + 8 + 8 * s);
        }
        if (kc + 2 < NC) {
            if (kc >= 1) {
                int ps = (kc - 1) % 3;
                mbar_wait(sbase + 8 + 8 * ps, wcnt[ps] & 1);
                wcnt[ps]++;
            }
            fill(kc + 2, (kc + 2) % 3);
        }
    }
#pragma unroll
    for (int c = NC - 3; c < NC; ++c) {
        int s = c % 3;
        mbar_wait(sbase + 8 + 8 * s, wcnt[s] & 1);
        wcnt[s]++;
    }

    __syncthreads();
    t5_fence_after();
    {
        int r = mBase + sp * 32 + lane;
#pragma unroll
        for (int half = 0; half < 2; ++half) {
            uint32_t cb[32];
            ldtm_x32(cb, tmem + ch * 64 + half * 32);
            t5_wait_ld();
            int colb = ch * 64 + half * 32;
            size_t ga = (size_t)r * DD + nBase + colb;
#pragma unroll
            for (int q = 0; q < 8; ++q) {
                float4 r4 = *reinterpret_cast<const float4*>(&res[ga + q * 4]);
                float4 o;
                o.x = __uint_as_float(cb[q * 4 + 0]) + sB[colb + q * 4 + 0] + r4.x;
                o.y = __uint_as_float(cb[q * 4 + 1]) + sB[colb + q * 4 + 1] + r4.y;
                o.z = __uint_as_float(cb[q * 4 + 2]) + sB[colb + q * 4 + 2] + r4.z;
                o.w = __uint_as_float(cb[q * 4 + 3]) + sB[colb + q * 4 + 3] + r4.w;
                *reinterpret_cast<float4*>(&outp[ga + q * 4]) = o;
            }
        }
    }
    t5_fence_before();
    __syncthreads();
    if (wid == 0) t5_dealloc(tmem, 128);
#else
    // fallback: mma.sync, single M=128 tile, K=4096
    float* sm = (float*)smraw;
    float* sX = sm;
    float* sW = sm + 2 * STAGE_F;
    const int tid = threadIdx.x;
    const int wid = tid >> 5, lane = tid & 31;
    const int g = lane >> 2, t = lane & 3;
    const int wm = (wid >> 2) * 64;
    const int wn = (wid & 3) * 32;
    const int nBase = blockIdx.x * 128;
    const int mBase = blockIdx.y * 128;
    uint32_t sXu = (uint32_t)__cvta_generic_to_shared(sX);
    uint32_t sWu = (uint32_t)__cvta_generic_to_shared(sW);
    const int NC = FF / 32;

    float acc[4][4][4];
#pragma unroll
    for (int mt = 0; mt < 4; ++mt)
#pragma unroll
        for (int nt = 0; nt < 4; ++nt)
#pragma unroll
            for (int k = 0; k < 4; ++k) acc[mt][nt][k] = 0.f;

    auto issue = [&](int kc, int st) {
        int k0 = kc * 32;
#pragma unroll
        for (int i = 0; i < 4; i++) {
            int j = tid + i * 256; int row = j >> 3; int c = (j & 7) * 4;
            cp16(sXu + (uint32_t)(((st * 128 + row) * TSTR) + c) * 4,
                 &Amat[(size_t)(mBase + row) * FF + k0 + c]);
        }
#pragma unroll
        for (int i = 0; i < 4; i++) {
            int j = tid + i * 256; int row = j >> 3; int c = (j & 7) * 4;
            cp16(sWu + (uint32_t)(((st * 128 + row) * TSTR) + c) * 4,
                 &Bmat[(size_t)(nBase + row) * FF + k0 + c]);
        }
        cp_commit();
    };

    issue(0, 0);
#pragma unroll 1
    for (int kc = 0; kc < NC; ++kc) {
        cp_wait<0>();
        __syncthreads();
        if (kc + 1 < NC) issue(kc + 1, (kc + 1) & 1);
        const float* xb = sX + (kc & 1) * STAGE_F;
        const float* wb = sW + (kc & 1) * STAGE_F;
#pragma unroll
        for (int kk = 0; kk < 4; ++kk) {
            int ks = kk * 8;
            uint32_t a[4][4], b[4][2];
#pragma unroll
            for (int mt = 0; mt < 4; ++mt) {
                int r = wm + mt * 16 + g;
                a[mt][0] = __float_as_uint(xb[r * TSTR + ks + t]);
                a[mt][1] = __float_as_uint(xb[(r + 8) * TSTR + ks + t]);
                a[mt][2] = __float_as_uint(xb[r * TSTR + ks + t + 4]);
                a[mt][3] = __float_as_uint(xb[(r + 8) * TSTR + ks + t + 4]);
            }
#pragma unroll
            for (int nt = 0; nt < 4; ++nt) {
                int cn = wn + nt * 8 + g;
                b[nt][0] = __float_as_uint(wb[cn * TSTR + ks + t]);
                b[nt][1] = __float_as_uint(wb[cn * TSTR + ks + t + 4]);
            }
#pragma unroll
            for (int mt = 0; mt < 4; ++mt)
#pragma unroll
                for (int nt = 0; nt < 4; ++nt) mma8(acc[mt][nt], a[mt], b[nt]);
        }
        __syncthreads();
    }

#pragma unroll
    for (int mt = 0; mt < 4; ++mt) {
        int r0 = wm + mt * 16 + g;
#pragma unroll
        for (int nt = 0; nt < 4; ++nt) {
            int c0 = wn + nt * 8 + 2 * t;
            int nc = nBase + c0;
            float bb0 = __ldg(&bias[nc]), bb1 = __ldg(&bias[nc + 1]);
#pragma unroll
            for (int half = 0; half < 2; ++half) {
                int r = r0 + 8 * half;
                size_t ga = (size_t)(mBase + r) * DD + nc;
                float2 r4 = *reinterpret_cast<const float2*>(&res[ga]);
                float2 o;
                o.x = acc[mt][nt][half * 2 + 0] + bb0 + r4.x;
                o.y = acc[mt][nt][half * 2 + 1] + bb1 + r4.y;
                *reinterpret_cast<float2*>(&outp[ga]) = o;
            }
        }
    }
#endif
}

// ---------------------------------------------------------------------------
extern "C" void kernel_launch(void* const* d_in, const int* in_sizes, int n_in,
                              void* d_out, int out_size) {
    const float* bv  = (const float*)d_in[0];
    const float* h0  = (const float*)d_in[1];
    const float* A   = (const float*)d_in[2];
    const float* Wb  = (const float*)d_in[3];
    const float* bb  = (const float*)d_in[4];
    const float* Wc  = (const float*)d_in[5];
    const float* bc  = (const float*)d_in[6];
    const float* Wd  = (const float*)d_in[7];
    const float* bd  = (const float*)d_in[8];
    const float* Wbg = (const float*)d_in[9];
    const float* bbg = (const float*)d_in[10];
    const float* Wcg = (const float*)d_in[11];
    const float* bcg = (const float*)d_in[12];
    const float* W1  = (const float*)d_in[13];
    const float* b1  = (const float*)d_in[14];
    const float* W2  = (const float*)d_in[15];
    const float* b2  = (const float*)d_in[16];
    const float* g1  = (const float*)d_in[17];
    const float* be1 = (const float*)d_in[18];
    const float* g2  = (const float*)d_in[19];
    const float* be2 = (const float*)d_in[20];

    float* out = (float*)d_out;
    const int X_ELEMS = BL * DD;
    int write_last = (out_size >= X_ELEMS + BSZN * HH) ? 1 : 0;
    float* lasth = out + X_ELEMS;

    cudaFuncSetAttribute(fused_ssm_t5, cudaFuncAttributeMaxDynamicSharedMemorySize, FUSED_SMEM);
    cudaFuncSetAttribute(ffn1_t5, cudaFuncAttributeMaxDynamicSharedMemorySize, FFN1_SMEM);
    cudaFuncSetAttribute(ffn2_t5, cudaFuncAttributeMaxDynamicSharedMemorySize, FFN2_SMEM);

    // (1) LN1+projB, (2) scan, (3) fused (raw fp32 weights; tf32 truncation in MMA)
    lnprojB_kernel<<<128, 256>>>(bv, g1, be1, Wb, bb, Wbg, bbg);
    scan_kernel<<<1, 64>>>(h0, A, lasth, write_last);
    {
        dim3 grid(OO / 128, BL / 256);   // (8, 16) = 128 CTAs
        fused_ssm_t5<<<grid, 256, FUSED_SMEM>>>(Wc, Wcg, Wd, bc, bcg, bd, bv);
    }
    // (4) LN2, (5) FFN1, (6) FFN2 (M=128, 2 CTAs/SM)
    ln_kernel<<<BL, 256>>>(g2, be2);

    float *pX3t, *pT, *pX3;
    cudaGetSymbolAddress((void**)&pX3t, g_x3t);
    cudaGetSymbolAddress((void**)&pT,   g_t);
    cudaGetSymbolAddress((void**)&pX3,  g_x3);

    {
        dim3 grid(FF / 256, BL / 256);   // (16, 16)
        ffn1_t5<<<grid, 256, FFN1_SMEM>>>(pX3t, W1, b1, pT);
    }
    {
        dim3 grid(DD / 128, BL / 128);   // (8, 32) = 256 CTAs, 2/SM
        ffn2_t5<<<grid, 256, FFN2_SMEM>>>(pT, W2, b2, pX3, out);
    }
}

// round 14
// speedup vs baseline: 1.1687x; 1.1687x over previous
#include <cuda_runtime.h>
#include <math.h>
#include <stdint.h>

#define BL   4096
#define DD   1024
#define HH   16
#define OO   1024
#define FF   4096
#define LSEQ 1024
#define BSZN 4

// Arch-specific (sm_103a) feature gate: tcgen05 only compiles in the 'a' pass.
#if defined(__CUDA_ARCH__)
#  if defined(__CUDA_ARCH_FEAT_SM103_ALL) || defined(__CUDA_ARCH_FEAT_SM100_ALL) || \
      (defined(__CUDA_ARCH_SPECIFIC__) && (__CUDA_ARCH_SPECIFIC__ >= 1000))
#    define T5_OK 1
#  else
#    define T5_OK 0
#  endif
#else
#  define T5_OK 0
#endif

// ---------------- scratch (device globals; no allocation allowed) ----------
__device__ float g_xlnt[BL * DD];
__device__ float g_Bg  [BL * HH];
__device__ float g_hs  [BL * HH];
__device__ float g_y   [BL * DD];
__device__ float g_x3  [BL * DD];
__device__ float g_x3t [BL * DD];
__device__ float g_t   [BL * FF];

// ---------------- basic helpers --------------------------------------------
__device__ __forceinline__ float tf32r(float f) {
    uint32_t u;
    asm("cvt.rna.tf32.f32 %0, %1;" : "=r"(u) : "f"(f));
    return __uint_as_float(u);
}
__device__ __forceinline__ float sigm(float x) { return 1.f / (1.f + __expf(-x)); }

__device__ __forceinline__ void cp16(uint32_t s, const float* gp) {
    asm volatile("cp.async.cg.shared.global [%0], [%1], 16;" :: "r"(s), "l"(gp));
}
__device__ __forceinline__ void cp_commit() { asm volatile("cp.async.commit_group;"); }
template <int N>
__device__ __forceinline__ void cp_wait() { asm volatile("cp.async.wait_group %0;" :: "n"(N)); }

// legacy mma.sync (fallback path)
__device__ __forceinline__ void mma8(float* c, const uint32_t* a, const uint32_t* b) {
    asm volatile(
        "mma.sync.aligned.m16n8k8.row.col.f32.tf32.tf32.f32 "
        "{%0,%1,%2,%3},{%4,%5,%6,%7},{%8,%9},{%0,%1,%2,%3};"
        : "+f"(c[0]), "+f"(c[1]), "+f"(c[2]), "+f"(c[3])
        : "r"(a[0]), "r"(a[1]), "r"(a[2]), "r"(a[3]), "r"(b[0]), "r"(b[1]));
}

__device__ __forceinline__ bool elect1() {
    uint32_t p;
    asm volatile("{\n\t.reg .pred p;\n\telect.sync _|p, 0xFFFFFFFF;\n\tselp.b32 %0,1,0,p;\n\t}"
                 : "=r"(p));
    return p != 0;
}
__device__ __forceinline__ void mbar_init(uint32_t a, uint32_t cnt) {
    asm volatile("mbarrier.init.shared.b64 [%0], %1;" :: "r"(a), "r"(cnt) : "memory");
}
__device__ __forceinline__ void mbar_wait(uint32_t a, uint32_t parity) {
    asm volatile(
        "{\n\t.reg .pred P;\n"
        "WL%=:\n\t"
        "mbarrier.try_wait.parity.acquire.cta.shared::cta.b64 P, [%0], %1, 0x989680;\n\t"
        "@P bra WD%=;\n\t"
        "bra.uni WL%=;\n"
        "WD%=:\n\t}"
        :: "r"(a), "r"(parity) : "memory");
}

// ---------------- tcgen05 helpers ------------------------------------------
__device__ __forceinline__ void t5_alloc(uint32_t slot, uint32_t ncols) {
    asm volatile("tcgen05.alloc.cta_group::1.sync.aligned.shared::cta.b32 [%0], %1;"
                 :: "r"(slot), "r"(ncols) : "memory");
}
__device__ __forceinline__ void t5_relinquish() {
    asm volatile("tcgen05.relinquish_alloc_permit.cta_group::1.sync.aligned;");
}
__device__ __forceinline__ void t5_dealloc(uint32_t base, uint32_t ncols) {
    asm volatile("tcgen05.dealloc.cta_group::1.sync.aligned.b32 %0, %1;"
                 :: "r"(base), "r"(ncols));
}
__device__ __forceinline__ void t5_commit(uint32_t mbar) {
    asm volatile("tcgen05.commit.cta_group::1.mbarrier::arrive::one.shared::cluster.b64 [%0];"
                 :: "r"(mbar) : "memory");
}
__device__ __forceinline__ void t5_wait_ld() {
    asm volatile("tcgen05.wait::ld.sync.aligned;" ::: "memory");
}
__device__ __forceinline__ void t5_fence_after() {
    asm volatile("tcgen05.fence::after_thread_sync;" ::: "memory");
}
__device__ __forceinline__ void t5_fence_before() {
    asm volatile("tcgen05.fence::before_thread_sync;" ::: "memory");
}
__device__ __forceinline__ void fence_proxy_async_s() {
    asm volatile("fence.proxy.async.shared::cta;" ::: "memory");
}

#define IDESC_TF32 ((1u << 4) | (2u << 7) | (2u << 10) | ((128u / 8) << 17) | ((128u / 16) << 24))

__device__ __forceinline__ uint64_t mkdesc(uint32_t addr) {
    return ((uint64_t)2 << 61) | ((uint64_t)1 << 46) | ((uint64_t)64 << 32)
         | ((uint64_t)1 << 16) | ((addr >> 4) & 0x3FFF);
}
__device__ __forceinline__ void mma_tf32(uint32_t d, uint64_t a, uint64_t b, bool en) {
    uint32_t e = en ? 1u : 0u;
    asm volatile(
        "{\n\t.reg .pred p;\n\t"
        "setp.ne.u32 p, %4, 0;\n\t"
        "tcgen05.mma.cta_group::1.kind::tf32 [%0], %1, %2, %3, {%5, %5, %5, %5}, p;\n\t}"
        :: "r"(d), "l"(a), "l"(b), "r"(IDESC_TF32), "r"(e), "r"(0u) : "memory");
}
__device__ __forceinline__ void ldtm_x16(uint32_t* r, uint32_t a) {
    asm volatile(
        "tcgen05.ld.sync.aligned.32x32b.x16.b32 "
        "{%0,%1,%2,%3,%4,%5,%6,%7,%8,%9,%10,%11,%12,%13,%14,%15}, [%16];"
        : "=r"(r[0]),  "=r"(r[1]),  "=r"(r[2]),  "=r"(r[3]),
          "=r"(r[4]),  "=r"(r[5]),  "=r"(r[6]),  "=r"(r[7]),
          "=r"(r[8]),  "=r"(r[9]),  "=r"(r[10]), "=r"(r[11]),
          "=r"(r[12]), "=r"(r[13]), "=r"(r[14]), "=r"(r[15])
        : "r"(a));
}
__device__ __forceinline__ void ldtm_x32(uint32_t* r, uint32_t a) {
    asm volatile(
        "tcgen05.ld.sync.aligned.32x32b.x32.b32 "
        "{%0,%1,%2,%3,%4,%5,%6,%7,%8,%9,%10,%11,%12,%13,%14,%15,"
        "%16,%17,%18,%19,%20,%21,%22,%23,%24,%25,%26,%27,%28,%29,%30,%31}, [%32];"
        : "=r"(r[0]),  "=r"(r[1]),  "=r"(r[2]),  "=r"(r[3]),
          "=r"(r[4]),  "=r"(r[5]),  "=r"(r[6]),  "=r"(r[7]),
          "=r"(r[8]),  "=r"(r[9]),  "=r"(r[10]), "=r"(r[11]),
          "=r"(r[12]), "=r"(r[13]), "=r"(r[14]), "=r"(r[15]),
          "=r"(r[16]), "=r"(r[17]), "=r"(r[18]), "=r"(r[19]),
          "=r"(r[20]), "=r"(r[21]), "=r"(r[22]), "=r"(r[23]),
          "=r"(r[24]), "=r"(r[25]), "=r"(r[26]), "=r"(r[27]),
          "=r"(r[28]), "=r"(r[29]), "=r"(r[30]), "=r"(r[31])
        : "r"(a));
}

// ---------------- fused LN1 + B-projection ----------------------------------
__global__ __launch_bounds__(256) void lnprojB_kernel(
    const float* __restrict__ bv,
    const float* __restrict__ g1, const float* __restrict__ be1,
    const float* __restrict__ Wb, const float* __restrict__ bb,
    const float* __restrict__ Wbg, const float* __restrict__ bbg)
{
    int tid = threadIdx.x, warp = tid >> 5, lane = tid & 31;
#pragma unroll 1
    for (int rr = 0; rr < 4; ++rr) {
        int row = blockIdx.x * 32 + warp * 4 + rr;
        const float4* x4 = (const float4*)(bv + (size_t)row * DD);
        float4 xv[8];
        float s = 0.f, s2 = 0.f;
#pragma unroll
        for (int j = 0; j < 8; ++j) {
            xv[j] = x4[lane + 32 * j];
            s  += xv[j].x + xv[j].y + xv[j].z + xv[j].w;
            s2 += xv[j].x * xv[j].x + xv[j].y * xv[j].y
                + xv[j].z * xv[j].z + xv[j].w * xv[j].w;
        }
#pragma unroll
        for (int o = 16; o > 0; o >>= 1) {
            s  += __shfl_xor_sync(0xffffffffu, s,  o);
            s2 += __shfl_xor_sync(0xffffffffu, s2, o);
        }
        float mean = s * (1.0f / DD);
        float rstd = rsqrtf(s2 * (1.0f / DD) - mean * mean + 1e-5f);
        float4* xt4 = (float4*)(g_xlnt + (size_t)row * DD);
#pragma unroll
        for (int j = 0; j < 8; ++j) {
            float4 g4 = __ldg(&((const float4*)g1)[lane + 32 * j]);
            float4 b4 = __ldg(&((const float4*)be1)[lane + 32 * j]);
            xv[j].x = (xv[j].x - mean) * rstd * g4.x + b4.x;
            xv[j].y = (xv[j].y - mean) * rstd * g4.y + b4.y;
            xv[j].z = (xv[j].z - mean) * rstd * g4.z + b4.z;
            xv[j].w = (xv[j].w - mean) * rstd * g4.w + b4.w;
            float4 ot;
            ot.x = tf32r(xv[j].x); ot.y = tf32r(xv[j].y);
            ot.z = tf32r(xv[j].z); ot.w = tf32r(xv[j].w);
            xt4[lane + 32 * j] = ot;
        }
#pragma unroll 1
        for (int h = 0; h < HH; ++h) {
            const float4* wb4 = (const float4*)(Wb  + (size_t)h * DD);
            const float4* wg4 = (const float4*)(Wbg + (size_t)h * DD);
            float sb = 0.f, sg = 0.f;
#pragma unroll
            for (int j = 0; j < 8; ++j) {
                float4 w0 = __ldg(&wb4[lane + 32 * j]);
                float4 w1 = __ldg(&wg4[lane + 32 * j]);
                sb += xv[j].x * w0.x + xv[j].y * w0.y + xv[j].z * w0.z + xv[j].w * w0.w;
                sg += xv[j].x * w1.x + xv[j].y * w1.y + xv[j].z * w1.z + xv[j].w * w1.w;
            }
#pragma unroll
            for (int o = 16; o > 0; o >>= 1) {
                sb += __shfl_down_sync(0xffffffffu, sb, o);
                sg += __shfl_down_sync(0xffffffffu, sg, o);
            }
            if (lane == 0) {
                float bval = sb + bb[h];
                float gval = sg + bbg[h];
                g_Bg[(size_t)row * HH + h] = bval * (1.f / (1.f + expf(-gval)));
            }
        }
    }
}

// ---------------- LayerNorm (LN2) — warp per row -----------------------------
__global__ __launch_bounds__(256) void ln2_kernel(const float* __restrict__ gw,
                                                  const float* __restrict__ bw) {
    int tid = threadIdx.x, warp = tid >> 5, lane = tid & 31;
    int row = blockIdx.x * 8 + warp;
    const float4* x4 = (const float4*)(g_y + (size_t)row * DD);
    float4 xv[8];
    float s = 0.f, s2 = 0.f;
#pragma unroll
    for (int j = 0; j < 8; ++j) {
        xv[j] = x4[lane + 32 * j];
        s  += xv[j].x + xv[j].y + xv[j].z + xv[j].w;
        s2 += xv[j].x * xv[j].x + xv[j].y * xv[j].y
            + xv[j].z * xv[j].z + xv[j].w * xv[j].w;
    }
#pragma unroll
    for (int o = 16; o > 0; o >>= 1) {
        s  += __shfl_xor_sync(0xffffffffu, s,  o);
        s2 += __shfl_xor_sync(0xffffffffu, s2, o);
    }
    float mean = s * (1.0f / DD);
    float rstd = rsqrtf(s2 * (1.0f / DD) - mean * mean + 1e-5f);
    float4* d4 = (float4*)(g_x3 + (size_t)row * DD);
    float4* t4 = (float4*)(g_x3t + (size_t)row * DD);
#pragma unroll
    for (int j = 0; j < 8; ++j) {
        float4 g4 = __ldg(&((const float4*)gw)[lane + 32 * j]);
        float4 b4 = __ldg(&((const float4*)bw)[lane + 32 * j]);
        float4 o;
        o.x = (xv[j].x - mean) * rstd * g4.x + b4.x;
        o.y = (xv[j].y - mean) * rstd * g4.y + b4.y;
        o.z = (xv[j].z - mean) * rstd * g4.z + b4.z;
        o.w = (xv[j].w - mean) * rstd * g4.w + b4.w;
        d4[lane + 32 * j] = o;
        float4 ot;
        ot.x = tf32r(o.x); ot.y = tf32r(o.y); ot.z = tf32r(o.z); ot.w = tf32r(o.w);
        t4[lane + 32 * j] = ot;
    }
}

// ---------------- selective scan — chunked parallel (1 block, 1024 thr) -----
__global__ __launch_bounds__(1024) void scan_kernel(
    const float* __restrict__ h0, const float* __restrict__ A,
    float* __restrict__ lasth, int write_last)
{
    __shared__ float sc[1024];
    __shared__ float hin[64 * 17];
    int t = threadIdx.x;
    int chain = t >> 4;        // 0..63
    int ck = t & 15;           // chunk 0..15
    int b = chain / HH, h = chain % HH;
    float dA = expf(A[h]);
    const float* bp = g_Bg + ((size_t)b * LSEQ + ck * 64) * HH + h;

    // phase 1: chunk-local partial state (zero init)
    float s = 0.f;
#pragma unroll 4
    for (int i = 0; i < 64; i++) s = dA * s + bp[(size_t)i * HH];
    sc[t] = s;
    // dA^64
    float p = dA;
#pragma unroll
    for (int i = 0; i < 6; i++) p = p * p;
    __syncthreads();

    // phase 2: per-chain carry combine (64 chains parallel, 16-step serial)
    if (ck == 0) {
        float hc = h0[b * HH + h];
        hin[chain * 17 + 0] = hc;
#pragma unroll 1
        for (int c = 0; c < 16; c++) {
            hc = p * hc + sc[chain * 16 + c];
            hin[chain * 17 + c + 1] = hc;
        }
        if (write_last) lasth[b * HH + h] = hc;
    }
    __syncthreads();

    // phase 3: recompute chunk from correct carry, write states
    float hc = hin[chain * 17 + ck];
    float* hp = g_hs + ((size_t)b * LSEQ + ck * 64) * HH + h;
#pragma unroll 4
    for (int i = 0; i < 64; i++) {
        hc = dA * hc + bp[(size_t)i * HH];
        hp[(size_t)i * HH] = hc;
    }
}

// ---------------- fallback mma.sync GEMM pass -------------------------------
#define TSTR 36
#define STAGE_F (128 * TSTR)

template <bool DUAL>
__device__ __forceinline__ void fb_gemm_pass(
    const float* __restrict__ W0, const float* __restrict__ W1p,
    const float* sX, const float* sWc, const float* sWg,
    uint32_t sXu, uint32_t sWcu, uint32_t sWgu,
    int tid, int g, int t, int wm, int wn, int mBase, int nBase,
    float (*accC)[4][4], float (*accG)[4][4])
{
    auto issue = [&](int kc, int st) {
        int k0 = kc * 32;
#pragma unroll
        for (int i = 0; i < 4; i++) {
            int j = tid + i * 256; int row = j >> 3; int c = (j & 7) * 4;
            cp16(sXu + (uint32_t)(((st * 128 + row) * TSTR) + c) * 4,
                 &g_xlnt[(size_t)(mBase + row) * DD + k0 + c]);
        }
#pragma unroll
        for (int i = 0; i < 4; i++) {
            int j = tid + i * 256; int row = j >> 3; int c = (j & 7) * 4;
            cp16(sWcu + (uint32_t)(((st * 128 + row) * TSTR) + c) * 4,
                 &W0[(size_t)(nBase + row) * DD + k0 + c]);
        }
        if (DUAL) {
#pragma unroll
            for (int i = 0; i < 4; i++) {
                int j = tid + i * 256; int row = j >> 3; int c = (j & 7) * 4;
                cp16(sWgu + (uint32_t)(((st * 128 + row) * TSTR) + c) * 4,
                     &W1p[(size_t)(nBase + row) * DD + k0 + c]);
            }
        }
        cp_commit();
    };

    issue(0, 0);
#pragma unroll 1
    for (int kc = 0; kc < 32; ++kc) {
        cp_wait<0>();
        __syncthreads();
        if (kc + 1 < 32) issue(kc + 1, (kc + 1) & 1);
        const float* xb  = sX  + (kc & 1) * STAGE_F;
        const float* wcb = sWc + (kc & 1) * STAGE_F;
        const float* wgb = sWg + (kc & 1) * STAGE_F;
#pragma unroll
        for (int kk = 0; kk < 4; ++kk) {
            int ks = kk * 8;
            uint32_t a[4][4];
#pragma unroll
            for (int mt = 0; mt < 4; ++mt) {
                int r = wm + mt * 16 + g;
                a[mt][0] = __float_as_uint(xb[r * TSTR + ks + t]);
                a[mt][1] = __float_as_uint(xb[(r + 8) * TSTR + ks + t]);
                a[mt][2] = __float_as_uint(xb[r * TSTR + ks + t + 4]);
                a[mt][3] = __float_as_uint(xb[(r + 8) * TSTR + ks + t + 4]);
            }
            uint32_t bC[4][2], bG[4][2];
#pragma unroll
            for (int nt = 0; nt < 4; ++nt) {
                int cn = wn + nt * 8 + g;
                bC[nt][0] = __float_as_uint(wcb[cn * TSTR + ks + t]);
                bC[nt][1] = __float_as_uint(wcb[cn * TSTR + ks + t + 4]);
                if (DUAL) {
                    bG[nt][0] = __float_as_uint(wgb[cn * TSTR + ks + t]);
                    bG[nt][1] = __float_as_uint(wgb[cn * TSTR + ks + t + 4]);
                }
            }
#pragma unroll
            for (int mt = 0; mt < 4; ++mt)
#pragma unroll
                for (int nt = 0; nt < 4; ++nt) {
                    mma8(accC[mt][nt], a[mt], bC[nt]);
                    if (DUAL) mma8(accG[mt][nt], a[mt], bG[nt]);
                }
        }
        __syncthreads();
    }
}

// ============================================================================
// Fused SSM kernel — flattened 544-chunk pipeline (tcgen05), raw fp32 weights.
// ============================================================================
#define F_HS   2048
#define F_ST   19456
#define F_STSZ 65536
#define FUSED_SMEM (19456 + 3 * 65536 + 1024)
#define NCH_TOT (17 * 32)

__global__ __launch_bounds__(256, 1)
void fused_ssm_t5(const float* __restrict__ Wc, const float* __restrict__ Wcg,
                  const float* __restrict__ Wd,
                  const float* __restrict__ bc, const float* __restrict__ bcg,
                  const float* __restrict__ bd, const float* __restrict__ bv)
{
    extern __shared__ char smraw[];
#if T5_OK
    uint32_t sraw = (uint32_t)__cvta_generic_to_shared(smraw);
    uint32_t sbase = (sraw + 1023) & ~1023u;
    float* smf = (float*)(smraw + (sbase - sraw));
    float* sBC = smf + 32;
    float* sBG = smf + 160;
    float* sHS = smf + F_HS / 4;

    const int tid = threadIdx.x;
    const int wid = tid >> 5, lane = tid & 31;
    const int sp = wid & 3, ch = wid >> 2;
    const int mBase = blockIdx.y * 256;
    const int nBase = blockIdx.x * 128;

    if (wid == 0) t5_alloc(sbase, 512);
    if (tid == 0) {
        mbar_init(sbase + 8, 1);
        mbar_init(sbase + 16, 1);
        mbar_init(sbase + 24, 1);
    }
    for (int i = tid; i < 256 * 16; i += 256) {
        int r = i >> 4, h = i & 15;
        sHS[r * 17 + h] = g_hs[(size_t)(mBase + r) * HH + h];
    }
    __syncthreads();
    uint32_t tmem;
    asm volatile("ld.shared.b32 %0, [%1];" : "=r"(tmem) : "r"(sbase));
    if (wid == 0) t5_relinquish();

    float ssm[128];
#pragma unroll
    for (int i = 0; i < 128; i++) ssm[i] = 0.f;

    auto fill = [&](int cg) {
        int head = cg >> 5, kc = cg & 31, st = cg % 3;
        bool dual = (head < 16);
        const float* Wc_h = dual ? (Wc + (size_t)head * OO * DD) : Wd;
        const float* Wg_h = Wcg + (size_t)(dual ? head : 0) * OO * DD;
        uint32_t sa = sbase + F_ST + st * F_STSZ;
        int k0 = kc * 32;
#pragma unroll
        for (int i = 0; i < 8; i++) {
            int id = tid + i * 256;
            int row = id >> 3, c = (id & 7) * 16;
            uint32_t off = (uint32_t)(row * 128 + c);
            uint32_t sw = off ^ ((off >> 3) & 0x70);
            cp16(sa + sw, &g_xlnt[(size_t)(mBase + row) * DD + k0 + (c >> 2)]);
        }
#pragma unroll
        for (int i = 0; i < 4; i++) {
            int id = tid + i * 256;
            int row = id >> 3, c = (id & 7) * 16;
            uint32_t off = (uint32_t)(row * 128 + c);
            uint32_t sw = off ^ ((off >> 3) & 0x70);
            cp16(sa + 32768 + sw, &Wc_h[(size_t)(nBase + row) * DD + k0 + (c >> 2)]);
            if (dual)
                cp16(sa + 49152 + sw, &Wg_h[(size_t)(nBase + row) * DD + k0 + (c >> 2)]);
        }
        cp_commit();
    };

    auto epilogue = [&](int h) {
        bool dual = (h < 16);
        if (tid < 128) {
            sBC[tid] = dual ? bc[h * OO + nBase + tid] : bd[nBase + tid];
        } else if (dual) {
            sBG[tid - 128] = bcg[h * OO + nBase + (tid - 128)];
        }
        __syncthreads();
        t5_fence_after();
#pragma unroll
        for (int s = 0; s < 2; ++s) {
            float hsv = 1.f;
            if (dual) hsv = sHS[(s * 128 + sp * 32 + lane) * 17 + h];
#pragma unroll
            for (int q = 0; q < 4; ++q) {
                uint32_t cb[16], gb[16];
                uint32_t ca = tmem + s * 128 + ch * 64 + q * 16;
                ldtm_x16(cb, ca);
                if (dual) ldtm_x16(gb, ca + 256);
                t5_wait_ld();
#pragma unroll
                for (int j = 0; j < 16; ++j) {
                    int col = ch * 64 + q * 16 + j;
                    float cc = __uint_as_float(cb[j]) + sBC[col];
                    if (dual) {
                        float gg = __uint_as_float(gb[j]) + sBG[col];
                        ssm[s * 64 + q * 16 + j] += hsv * cc * sigm(gg);
                    } else {
                        ssm[s * 64 + q * 16 + j] += cc;
                    }
                }
            }
        }
        t5_fence_before();
        __syncthreads();
    };

    fill(0);
    fill(1);
#pragma unroll 1
    for (int cg = 0; cg < NCH_TOT; ++cg) {
        int kc = cg & 31, head = cg >> 5, s = cg % 3;
        if (kc == 0 && head > 0) {
            mbar_wait(sbase + 8 + 8 * ((cg - 1) % 3), ((cg - 1) / 3) & 1);
            epilogue(head - 1);
        }
        if (cg < NCH_TOT - 1) cp_wait<1>(); else cp_wait<0>();
        fence_proxy_async_s();
        __syncthreads();
        if (wid == 0 && elect1()) {
            bool dual = (head < 16);
            uint32_t sa = sbase + F_ST + s * F_STSZ;
            uint64_t dA0 = mkdesc(sa), dA1 = mkdesc(sa + 16384);
            uint64_t dBc = mkdesc(sa + 32768), dBg = mkdesc(sa + 49152);
#pragma unroll
            for (int ks = 0; ks < 4; ++ks) {
                bool en = !(kc == 0 && ks == 0);
                uint64_t o = (uint64_t)(ks * 2);
                mma_tf32(tmem + 0,   dA0 + o, dBc + o, en);
                mma_tf32(tmem + 128, dA1 + o, dBc + o, en);
                if (dual) {
                    mma_tf32(tmem + 256, dA0 + o, dBg + o, en);
                    mma_tf32(tmem + 384, dA1 + o, dBg + o, en);
                }
            }
            t5_commit(sbase + 8 + 8 * s);
        }
        if (cg + 2 < NCH_TOT) {
            if (cg >= 1)
                mbar_wait(sbase + 8 + 8 * ((cg - 1) % 3), ((cg - 1) / 3) & 1);
            fill(cg + 2);
        }
    }
    mbar_wait(sbase + 8 + 8 * ((NCH_TOT - 1) % 3), ((NCH_TOT - 1) / 3) & 1);
    epilogue(16);

#pragma unroll
    for (int s = 0; s < 2; ++s) {
        int r = mBase + s * 128 + sp * 32 + lane;
        size_t ga = (size_t)r * DD + nBase + ch * 64;
#pragma unroll
        for (int q = 0; q < 16; ++q) {
            float4 b4 = *reinterpret_cast<const float4*>(&bv[ga + q * 4]);
            float4 o;
            o.x = b4.x + ssm[s * 64 + q * 4 + 0];
            o.y = b4.y + ssm[s * 64 + q * 4 + 1];
            o.z = b4.z + ssm[s * 64 + q * 4 + 2];
            o.w = b4.w + ssm[s * 64 + q * 4 + 3];
            *reinterpret_cast<float4*>(&g_y[ga + q * 4]) = o;
        }
    }

    __syncthreads();
    if (wid == 0) t5_dealloc(tmem, 512);
#else
    float* sm  = (float*)smraw;
    float* sX  = sm;
    float* sWc = sm + 2 * STAGE_F;
    float* sWg = sm + 4 * STAGE_F;
    float* sS  = sm + 6 * STAGE_F;
    float* sHS = sS + 128 * 136;

    const int tid = threadIdx.x;
    const int wid = tid >> 5, lane = tid & 31;
    const int g = lane >> 2, t = lane & 3;
    const int wm = (wid >> 2) * 64;
    const int wn = (wid & 3) * 32;
    const int nBase = blockIdx.x * 128;
    uint32_t sXu  = (uint32_t)__cvta_generic_to_shared(sX);
    uint32_t sWcu = (uint32_t)__cvta_generic_to_shared(sWc);
    uint32_t sWgu = (uint32_t)__cvta_generic_to_shared(sWg);

    for (int sub = 0; sub < 2; ++sub) {
        const int mBase = blockIdx.y * 256 + sub * 128;
        for (int i = tid; i < 128 * 136; i += 256) sS[i] = 0.f;
        for (int i = tid; i < 128 * 16; i += 256) {
            int r = i >> 4, h = i & 15;
            sHS[r * 17 + h] = g_hs[(size_t)(mBase + r) * HH + h];
        }
        __syncthreads();

        float accC[4][4][4], accG[4][4][4];
        for (int pass = 0; pass < HH; ++pass) {
#pragma unroll
            for (int mt = 0; mt < 4; ++mt)
#pragma unroll
                for (int nt = 0; nt < 4; ++nt)
#pragma unroll
                    for (int k = 0; k < 4; ++k) { accC[mt][nt][k] = 0.f; accG[mt][nt][k] = 0.f; }

            fb_gemm_pass<true>(Wc + (size_t)pass * OO * DD,
                               Wcg + (size_t)pass * OO * DD,
                               sX, sWc, sWg, sXu, sWcu, sWgu,
                               tid, g, t, wm, wn, mBase, nBase, accC, accG);

#pragma unroll
            for (int mt = 0; mt < 4; ++mt) {
                int r0 = wm + mt * 16 + g;
                float hs0 = sHS[r0 * 17 + pass];
                float hs1 = sHS[(r0 + 8) * 17 + pass];
#pragma unroll
                for (int nt = 0; nt < 4; ++nt) {
                    int c0 = wn + nt * 8 + 2 * t;
                    int cg0 = nBase + c0;
                    float bc0 = __ldg(&bc[pass * OO + cg0]);
                    float bc1 = __ldg(&bc[pass * OO + cg0 + 1]);
                    float bg0 = __ldg(&bcg[pass * OO + cg0]);
                    float bg1 = __ldg(&bcg[pass * OO + cg0 + 1]);
                    float* s0 = &sS[r0 * 136 + c0];
                    float* s1 = &sS[(r0 + 8) * 136 + c0];
                    s0[0] += hs0 * (accC[mt][nt][0] + bc0) * sigm(accG[mt][nt][0] + bg0);
                    s0[1] += hs0 * (accC[mt][nt][1] + bc1) * sigm(accG[mt][nt][1] + bg1);
                    s1[0] += hs1 * (accC[mt][nt][2] + bc0) * sigm(accG[mt][nt][2] + bg0);
                    s1[1] += hs1 * (accC[mt][nt][3] + bc1) * sigm(accG[mt][nt][3] + bg1);
                }
            }
        }

#pragma unroll
        for (int mt = 0; mt < 4; ++mt)
#pragma unroll
            for (int nt = 0; nt < 4; ++nt)
#pragma unroll
                for (int k = 0; k < 4; ++k) accC[mt][nt][k] = 0.f;

        fb_gemm_pass<false>(Wd, Wd, sX, sWc, sWg, sXu, sWcu, sWgu,
                            tid, g, t, wm, wn, mBase, nBase, accC, accG);

#pragma unroll
        for (int mt = 0; mt < 4; ++mt) {
            int r0 = wm + mt * 16 + g;
#pragma unroll
            for (int nt = 0; nt < 4; ++nt) {
                int c0 = wn + nt * 8 + 2 * t;
                int cg0 = nBase + c0;
                float bd0 = __ldg(&bd[cg0]);
                float bd1 = __ldg(&bd[cg0 + 1]);
                float* s0 = &sS[r0 * 136 + c0];
                float* s1 = &sS[(r0 + 8) * 136 + c0];
                s0[0] += accC[mt][nt][0] + bd0;
                s0[1] += accC[mt][nt][1] + bd1;
                s1[0] += accC[mt][nt][2] + bd0;
                s1[1] += accC[mt][nt][3] + bd1;
            }
        }

#pragma unroll
        for (int mt = 0; mt < 4; ++mt) {
            int r0 = wm + mt * 16 + g;
#pragma unroll
            for (int nt = 0; nt < 4; ++nt) {
                int c0 = wn + nt * 8 + 2 * t;
#pragma unroll
                for (int half = 0; half < 2; ++half) {
                    int r = r0 + 8 * half;
                    size_t gaddr = (size_t)(mBase + r) * DD + nBase + c0;
                    float2 bvv = *reinterpret_cast<const float2*>(&bv[gaddr]);
                    float2 sv  = *reinterpret_cast<float2*>(&sS[r * 136 + c0]);
                    float2 o; o.x = bvv.x + sv.x; o.y = bvv.y + sv.y;
                    *reinterpret_cast<float2*>(&g_y[gaddr]) = o;
                }
            }
        }
        __syncthreads();
    }
#endif
}

// ============================================================================
// FFN1: M=256 x N=256 per CTA. out = tf32r(gelu(A@B.T+b))
// ============================================================================
#define FFN1_SMEM (2048 + 3 * 65536 + 1024)

__global__ __launch_bounds__(256, 1)
void ffn1_t5(const float* __restrict__ Amat, const float* __restrict__ Bmat,
             const float* __restrict__ bias, float* __restrict__ outp)
{
    extern __shared__ char smraw[];
#if T5_OK
    uint32_t sraw = (uint32_t)__cvta_generic_to_shared(smraw);
    uint32_t sbase = (sraw + 1023) & ~1023u;
    float* smf = (float*)(smraw + (sbase - sraw));
    float* sB = smf + 32;

    const int tid = threadIdx.x;
    const int wid = tid >> 5, lane = tid & 31;
    const int sp = wid & 3, ch = wid >> 2;
    const int mBase = blockIdx.y * 256;
    const int nBase = blockIdx.x * 256;
    const int NC = DD / 32;

    if (wid == 0) t5_alloc(sbase, 512);
    if (tid == 0) {
        mbar_init(sbase + 8, 1);
        mbar_init(sbase + 16, 1);
        mbar_init(sbase + 24, 1);
    }
    sB[tid] = bias[nBase + tid];
    __syncthreads();
    uint32_t tmem;
    asm volatile("ld.shared.b32 %0, [%1];" : "=r"(tmem) : "r"(sbase));
    if (wid == 0) t5_relinquish();

    uint32_t wcnt[3] = {0, 0, 0};

    auto fill = [&](int kc, int st) {
        uint32_t sa = sbase + 2048 + st * 65536;
        int k0 = kc * 32;
#pragma unroll
        for (int i = 0; i < 8; i++) {
            int id = tid + i * 256;
            int row = id >> 3, c = (id & 7) * 16;
            uint32_t off = (uint32_t)(row * 128 + c);
            uint32_t sw = off ^ ((off >> 3) & 0x70);
            cp16(sa + sw, &Amat[(size_t)(mBase + row) * DD + k0 + (c >> 2)]);
        }
#pragma unroll
        for (int i = 0; i < 8; i++) {
            int id = tid + i * 256;
            int row = id >> 3, c = (id & 7) * 16;
            uint32_t off = (uint32_t)(row * 128 + c);
            uint32_t sw = off ^ ((off >> 3) & 0x70);
            cp16(sa + 32768 + sw, &Bmat[(size_t)(nBase + row) * DD + k0 + (c >> 2)]);
        }
        cp_commit();
    };

    fill(0, 0);
    fill(1, 1);
#pragma unroll 1
    for (int kc = 0; kc < NC; ++kc) {
        int s = kc % 3;
        if (kc < NC - 1) cp_wait<1>(); else cp_wait<0>();
        fence_proxy_async_s();
        __syncthreads();
        if (wid == 0 && elect1()) {
            uint32_t sa = sbase + 2048 + s * 65536;
            uint64_t dA0 = mkdesc(sa), dA1 = mkdesc(sa + 16384);
            uint64_t dB0 = mkdesc(sa + 32768), dB1 = mkdesc(sa + 49152);
#pragma unroll
            for (int ks = 0; ks < 4; ++ks) {
                bool en = !(kc == 0 && ks == 0);
                uint64_t o = (uint64_t)(ks * 2);
                mma_tf32(tmem + 0,   dA0 + o, dB0 + o, en);
                mma_tf32(tmem + 128, dA0 + o, dB1 + o, en);
                mma_tf32(tmem + 256, dA1 + o, dB0 + o, en);
                mma_tf32(tmem + 384, dA1 + o, dB1 + o, en);
            }
            t5_commit(sbase + 8 + 8 * s);
        }
        if (kc + 2 < NC) {
            if (kc >= 1) {
                int ps = (kc - 1) % 3;
                mbar_wait(sbase + 8 + 8 * ps, wcnt[ps] & 1);
                wcnt[ps]++;
            }
            fill(kc + 2, (kc + 2) % 3);
        }
    }
#pragma unroll
    for (int c = NC - 3; c < NC; ++c) {
        int s = c % 3;
        mbar_wait(sbase + 8 + 8 * s, wcnt[s] & 1);
        wcnt[s]++;
    }

    __syncthreads();
    t5_fence_after();
#pragma unroll
    for (int ms = 0; ms < 2; ++ms) {
        int r = mBase + ms * 128 + sp * 32 + lane;
#pragma unroll
        for (int ns = 0; ns < 2; ++ns) {
#pragma unroll
            for (int half = 0; half < 2; ++half) {
                uint32_t cb[32];
                ldtm_x32(cb, tmem + ms * 256 + ns * 128 + ch * 64 + half * 32);
                t5_wait_ld();
                int colb = ns * 128 + ch * 64 + half * 32;
                size_t ga = (size_t)r * FF + nBase + colb;
#pragma unroll
                for (int q = 0; q < 8; ++q) {
                    float4 o;
                    float v0 = __uint_as_float(cb[q * 4 + 0]) + sB[colb + q * 4 + 0];
                    float v1 = __uint_as_float(cb[q * 4 + 1]) + sB[colb + q * 4 + 1];
                    float v2 = __uint_as_float(cb[q * 4 + 2]) + sB[colb + q * 4 + 2];
                    float v3 = __uint_as_float(cb[q * 4 + 3]) + sB[colb + q * 4 + 3];
                    o.x = tf32r(0.5f * v0 * (1.0f + erff(v0 * 0.70710678118654752f)));
                    o.y = tf32r(0.5f * v1 * (1.0f + erff(v1 * 0.70710678118654752f)));
                    o.z = tf32r(0.5f * v2 * (1.0f + erff(v2 * 0.70710678118654752f)));
                    o.w = tf32r(0.5f * v3 * (1.0f + erff(v3 * 0.70710678118654752f)));
                    *reinterpret_cast<float4*>(&outp[ga + q * 4]) = o;
                }
            }
        }
    }
    t5_fence_before();
    __syncthreads();
    if (wid == 0) t5_dealloc(tmem, 512);
#else
    float* sm = (float*)smraw;
    float* sX = sm;
    float* sW = sm + 2 * STAGE_F;
    const int tid = threadIdx.x;
    const int wid = tid >> 5, lane = tid & 31;
    const int g = lane >> 2, t = lane & 3;
    const int wm = (wid >> 2) * 64;
    const int wn = (wid & 3) * 32;
    uint32_t sXu = (uint32_t)__cvta_generic_to_shared(sX);
    uint32_t sWu = (uint32_t)__cvta_generic_to_shared(sW);

    for (int ns = 0; ns < 2; ++ns) {
        const int nBase = blockIdx.x * 256 + ns * 128;
        for (int sub = 0; sub < 2; ++sub) {
            const int mBase = blockIdx.y * 256 + sub * 128;
            float acc[4][4][4];
#pragma unroll
            for (int mt = 0; mt < 4; ++mt)
#pragma unroll
                for (int nt = 0; nt < 4; ++nt)
#pragma unroll
                    for (int k = 0; k < 4; ++k) acc[mt][nt][k] = 0.f;

            auto issue = [&](int kc, int st) {
                int k0 = kc * 32;
#pragma unroll
                for (int i = 0; i < 4; i++) {
                    int j = tid + i * 256; int row = j >> 3; int c = (j & 7) * 4;
                    cp16(sXu + (uint32_t)(((st * 128 + row) * TSTR) + c) * 4,
                         &Amat[(size_t)(mBase + row) * DD + k0 + c]);
                }
#pragma unroll
                for (int i = 0; i < 4; i++) {
                    int j = tid + i * 256; int row = j >> 3; int c = (j & 7) * 4;
                    cp16(sWu + (uint32_t)(((st * 128 + row) * TSTR) + c) * 4,
                         &Bmat[(size_t)(nBase + row) * DD + k0 + c]);
                }
                cp_commit();
            };

            issue(0, 0);
#pragma unroll 1
            for (int kc = 0; kc < 32; ++kc) {
                cp_wait<0>();
                __syncthreads();
                if (kc + 1 < 32) issue(kc + 1, (kc + 1) & 1);
                const float* xb = sX + (kc & 1) * STAGE_F;
                const float* wb = sW + (kc & 1) * STAGE_F;
#pragma unroll
                for (int kk = 0; kk < 4; ++kk) {
                    int ks = kk * 8;
                    uint32_t a[4][4], b[4][2];
#pragma unroll
                    for (int mt = 0; mt < 4; ++mt) {
                        int r = wm + mt * 16 + g;
                        a[mt][0] = __float_as_uint(xb[r * TSTR + ks + t]);
                        a[mt][1] = __float_as_uint(xb[(r + 8) * TSTR + ks + t]);
                        a[mt][2] = __float_as_uint(xb[r * TSTR + ks + t + 4]);
                        a[mt][3] = __float_as_uint(xb[(r + 8) * TSTR + ks + t + 4]);
                    }
#pragma unroll
                    for (int nt = 0; nt < 4; ++nt) {
                        int cn = wn + nt * 8 + g;
                        b[nt][0] = __float_as_uint(wb[cn * TSTR + ks + t]);
                        b[nt][1] = __float_as_uint(wb[cn * TSTR + ks + t + 4]);
                    }
#pragma unroll
                    for (int mt = 0; mt < 4; ++mt)
#pragma unroll
                        for (int nt = 0; nt < 4; ++nt) mma8(acc[mt][nt], a[mt], b[nt]);
                }
                __syncthreads();
            }

#pragma unroll
            for (int mt = 0; mt < 4; ++mt) {
                int r0 = wm + mt * 16 + g;
#pragma unroll
                for (int nt = 0; nt < 4; ++nt) {
                    int c0 = wn + nt * 8 + 2 * t;
                    int nc = nBase + c0;
                    float bb0 = __ldg(&bias[nc]), bb1 = __ldg(&bias[nc + 1]);
#pragma unroll
                    for (int half = 0; half < 2; ++half) {
                        int r = r0 + 8 * half;
                        size_t ga = (size_t)(mBase + r) * FF + nc;
                        float v0 = acc[mt][nt][half * 2 + 0] + bb0;
                        float v1 = acc[mt][nt][half * 2 + 1] + bb1;
                        v0 = 0.5f * v0 * (1.0f + erff(v0 * 0.70710678118654752f));
                        v1 = 0.5f * v1 * (1.0f + erff(v1 * 0.70710678118654752f));
                        float2 o; o.x = tf32r(v0); o.y = tf32r(v1);
                        *reinterpret_cast<float2*>(&outp[ga]) = o;
                    }
                }
            }
            __syncthreads();
        }
    }
#endif
}

// ============================================================================
// FFN2: M=256 x N=128, K=4096 (R12-proven). outp = res + A @ B.T + bias
// ============================================================================
#define G_ST   2048
#define G_STSZ 49152
#define GEMM_SMEM (2048 + 3 * 49152 + 1024)

__global__ __launch_bounds__(256, 1)
void ffn2_t5(const float* __restrict__ Amat, const float* __restrict__ Bmat,
             const float* __restrict__ bias, const float* __restrict__ res,
             float* __restrict__ outp)
{
    extern __shared__ char smraw[];
#if T5_OK
    uint32_t sraw = (uint32_t)__cvta_generic_to_shared(smraw);
    uint32_t sbase = (sraw + 1023) & ~1023u;
    float* smf = (float*)(smraw + (sbase - sraw));
    float* sB = smf + 32;

    const int tid = threadIdx.x;
    const int wid = tid >> 5, lane = tid & 31;
    const int sp = wid & 3, ch = wid >> 2;
    const int mBase = blockIdx.y * 256;
    const int nBase = blockIdx.x * 128;
    const int NC = FF / 32;

    if (wid == 0) t5_alloc(sbase, 512);
    if (tid == 0) {
        mbar_init(sbase + 8, 1);
        mbar_init(sbase + 16, 1);
        mbar_init(sbase + 24, 1);
    }
    if (tid < 128) sB[tid] = bias[nBase + tid];
    __syncthreads();
    uint32_t tmem;
    asm volatile("ld.shared.b32 %0, [%1];" : "=r"(tmem) : "r"(sbase));
    if (wid == 0) t5_relinquish();

    uint32_t wcnt[3] = {0, 0, 0};

    auto fill = [&](int kc, int st) {
        uint32_t sa = sbase + G_ST + st * G_STSZ;
        int k0 = kc * 32;
#pragma unroll
        for (int i = 0; i < 8; i++) {
            int id = tid + i * 256;
            int row = id >> 3, c = (id & 7) * 16;
            uint32_t off = (uint32_t)(row * 128 + c);
            uint32_t sw = off ^ ((off >> 3) & 0x70);
            cp16(sa + sw, &Amat[(size_t)(mBase + row) * FF + k0 + (c >> 2)]);
        }
#pragma unroll
        for (int i = 0; i < 4; i++) {
            int id = tid + i * 256;
            int row = id >> 3, c = (id & 7) * 16;
            uint32_t off = (uint32_t)(row * 128 + c);
            uint32_t sw = off ^ ((off >> 3) & 0x70);
            cp16(sa + 32768 + sw, &Bmat[(size_t)(nBase + row) * FF + k0 + (c >> 2)]);
        }
        cp_commit();
    };

    fill(0, 0);
    fill(1, 1);
#pragma unroll 1
    for (int kc = 0; kc < NC; ++kc) {
        int s = kc % 3;
        if (kc < NC - 1) cp_wait<1>(); else cp_wait<0>();
        fence_proxy_async_s();
        __syncthreads();
        if (wid == 0 && elect1()) {
            uint32_t sa = sbase + G_ST + s * G_STSZ;
            uint64_t dA0 = mkdesc(sa), dA1 = mkdesc(sa + 16384);
            uint64_t dB = mkdesc(sa + 32768);
#pragma unroll
            for (int ks = 0; ks < 4; ++ks) {
                bool en = !(kc == 0 && ks == 0);
                uint64_t o = (uint64_t)(ks * 2);
                mma_tf32(tmem + 0,   dA0 + o, dB + o, en);
                mma_tf32(tmem + 128, dA1 + o, dB + o, en);
            }
            t5_commit(sbase + 8 + 8 * s);
        }
        if (kc + 2 < NC) {
            if (kc >= 1) {
                int ps = (kc - 1) % 3;
                mbar_wait(sbase + 8 + 8 * ps, wcnt[ps] & 1);
                wcnt[ps]++;
            }
            fill(kc + 2, (kc + 2) % 3);
        }
    }
#pragma unroll
    for (int c = NC - 3; c < NC; ++c) {
        int s = c % 3;
        mbar_wait(sbase + 8 + 8 * s, wcnt[s] & 1);
        wcnt[s]++;
    }

    __syncthreads();
    t5_fence_after();
#pragma unroll
    for (int s = 0; s < 2; ++s) {
        int r = mBase + s * 128 + sp * 32 + lane;
#pragma unroll
        for (int half = 0; half < 2; ++half) {
            uint32_t cb[32];
            ldtm_x32(cb, tmem + s * 128 + ch * 64 + half * 32);
            t5_wait_ld();
            int colb = ch * 64 + half * 32;
            size_t ga = (size_t)r * DD + nBase + colb;
#pragma unroll
            for (int q = 0; q < 8; ++q) {
                float4 r4 = *reinterpret_cast<const float4*>(&res[ga + q * 4]);
                float4 o;
                o.x = __uint_as_float(cb[q * 4 + 0]) + sB[colb + q * 4 + 0] + r4.x;
                o.y = __uint_as_float(cb[q * 4 + 1]) + sB[colb + q * 4 + 1] + r4.y;
                o.z = __uint_as_float(cb[q * 4 + 2]) + sB[colb + q * 4 + 2] + r4.z;
                o.w = __uint_as_float(cb[q * 4 + 3]) + sB[colb + q * 4 + 3] + r4.w;
                *reinterpret_cast<float4*>(&outp[ga + q * 4]) = o;
            }
        }
    }
    t5_fence_before();
    __syncthreads();
    if (wid == 0) t5_dealloc(tmem, 512);
#else
    float* sm = (float*)smraw;
    float* sX = sm;
    float* sW = sm + 2 * STAGE_F;
    const int tid = threadIdx.x;
    const int wid = tid >> 5, lane = tid & 31;
    const int g = lane >> 2, t = lane & 3;
    const int wm = (wid >> 2) * 64;
    const int wn = (wid & 3) * 32;
    const int nBase = blockIdx.x * 128;
    uint32_t sXu = (uint32_t)__cvta_generic_to_shared(sX);
    uint32_t sWu = (uint32_t)__cvta_generic_to_shared(sW);
    const int NC = FF / 32;

    for (int sub = 0; sub < 2; ++sub) {
        const int mBase = blockIdx.y * 256 + sub * 128;
        float acc[4][4][4];
#pragma unroll
        for (int mt = 0; mt < 4; ++mt)
#pragma unroll
            for (int nt = 0; nt < 4; ++nt)
#pragma unroll
                for (int k = 0; k < 4; ++k) acc[mt][nt][k] = 0.f;

        auto issue = [&](int kc, int st) {
            int k0 = kc * 32;
#pragma unroll
            for (int i = 0; i < 4; i++) {
                int j = tid + i * 256; int row = j >> 3; int c = (j & 7) * 4;
                cp16(sXu + (uint32_t)(((st * 128 + row) * TSTR) + c) * 4,
                     &Amat[(size_t)(mBase + row) * FF + k0 + c]);
            }
#pragma unroll
            for (int i = 0; i < 4; i++) {
                int j = tid + i * 256; int row = j >> 3; int c = (j & 7) * 4;
                cp16(sWu + (uint32_t)(((st * 128 + row) * TSTR) + c) * 4,
                     &Bmat[(size_t)(nBase + row) * FF + k0 + c]);
            }
            cp_commit();
        };

        issue(0, 0);
#pragma unroll 1
        for (int kc = 0; kc < NC; ++kc) {
            cp_wait<0>();
            __syncthreads();
            if (kc + 1 < NC) issue(kc + 1, (kc + 1) & 1);
            const float* xb = sX + (kc & 1) * STAGE_F;
            const float* wb = sW + (kc & 1) * STAGE_F;
#pragma unroll
            for (int kk = 0; kk < 4; ++kk) {
                int ks = kk * 8;
                uint32_t a[4][4], b[4][2];
#pragma unroll
                for (int mt = 0; mt < 4; ++mt) {
                    int r = wm + mt * 16 + g;
                    a[mt][0] = __float_as_uint(xb[r * TSTR + ks + t]);
                    a[mt][1] = __float_as_uint(xb[(r + 8) * TSTR + ks + t]);
                    a[mt][2] = __float_as_uint(xb[r * TSTR + ks + t + 4]);
                    a[mt][3] = __float_as_uint(xb[(r + 8) * TSTR + ks + t + 4]);
                }
#pragma unroll
                for (int nt = 0; nt < 4; ++nt) {
                    int cn = wn + nt * 8 + g;
                    b[nt][0] = __float_as_uint(wb[cn * TSTR + ks + t]);
                    b[nt][1] = __float_as_uint(wb[cn * TSTR + ks + t + 4]);
                }
#pragma unroll
                for (int mt = 0; mt < 4; ++mt)
#pragma unroll
                    for (int nt = 0; nt < 4; ++nt) mma8(acc[mt][nt], a[mt], b[nt]);
            }
            __syncthreads();
        }

#pragma unroll
        for (int mt = 0; mt < 4; ++mt) {
            int r0 = wm + mt * 16 + g;
#pragma unroll
            for (int nt = 0; nt < 4; ++nt) {
                int c0 = wn + nt * 8 + 2 * t;
                int nc = nBase + c0;
                float bb0 = __ldg(&bias[nc]), bb1 = __ldg(&bias[nc + 1]);
#pragma unroll
                for (int half = 0; half < 2; ++half) {
                    int r = r0 + 8 * half;
                    size_t ga = (size_t)(mBase + r) * DD + nc;
                    float2 r4 = *reinterpret_cast<const float2*>(&res[ga]);
                    float2 o;
                    o.x = acc[mt][nt][half * 2 + 0] + bb0 + r4.x;
                    o.y = acc[mt][nt][half * 2 + 1] + bb1 + r4.y;
                    *reinterpret_cast<float2*>(&outp[ga]) = o;
                }
            }
        }
        __syncthreads();
    }
#endif
}

// ---------------------------------------------------------------------------
extern "C" void kernel_launch(void* const* d_in, const int* in_sizes, int n_in,
                              void* d_out, int out_size) {
    const float* bv  = (const float*)d_in[0];
    const float* h0  = (const float*)d_in[1];
    const float* A   = (const float*)d_in[2];
    const float* Wb  = (const float*)d_in[3];
    const float* bb  = (const float*)d_in[4];
    const float* Wc  = (const float*)d_in[5];
    const float* bc  = (const float*)d_in[6];
    const float* Wd  = (const float*)d_in[7];
    const float* bd  = (const float*)d_in[8];
    const float* Wbg = (const float*)d_in[9];
    const float* bbg = (const float*)d_in[10];
    const float* Wcg = (const float*)d_in[11];
    const float* bcg = (const float*)d_in[12];
    const float* W1  = (const float*)d_in[13];
    const float* b1  = (const float*)d_in[14];
    const float* W2  = (const float*)d_in[15];
    const float* b2  = (const float*)d_in[16];
    const float* g1  = (const float*)d_in[17];
    const float* be1 = (const float*)d_in[18];
    const float* g2  = (const float*)d_in[19];
    const float* be2 = (const float*)d_in[20];

    float* out = (float*)d_out;
    const int X_ELEMS = BL * DD;
    int write_last = (out_size >= X_ELEMS + BSZN * HH) ? 1 : 0;
    float* lasth = out + X_ELEMS;

    cudaFuncSetAttribute(fused_ssm_t5, cudaFuncAttributeMaxDynamicSharedMemorySize, FUSED_SMEM);
    cudaFuncSetAttribute(ffn1_t5, cudaFuncAttributeMaxDynamicSharedMemorySize, FFN1_SMEM);
    cudaFuncSetAttribute(ffn2_t5, cudaFuncAttributeMaxDynamicSharedMemorySize, GEMM_SMEM);

    // (1) LN1+projB, (2) parallel scan, (3) fused
    lnprojB_kernel<<<128, 256>>>(bv, g1, be1, Wb, bb, Wbg, bbg);
    scan_kernel<<<1, 1024>>>(h0, A, lasth, write_last);
    {
        dim3 grid(OO / 128, BL / 256);   // (8, 16) = 128 CTAs
        fused_ssm_t5<<<grid, 256, FUSED_SMEM>>>(Wc, Wcg, Wd, bc, bcg, bd, bv);
    }
    // (4) LN2 (warp-per-row), (5) FFN1, (6) FFN2 (M=256, R12 config)
    ln2_kernel<<<BL / 8, 256>>>(g2, be2);

    float *pX3t, *pT, *pX3;
    cudaGetSymbolAddress((void**)&pX3t, g_x3t);
    cudaGetSymbolAddress((void**)&pT,   g_t);
    cudaGetSymbolAddress((void**)&pX3,  g_x3);

    {
        dim3 grid(FF / 256, BL / 256);   // (16, 16)
        ffn1_t5<<<grid, 256, FFN1_SMEM>>>(pX3t, W1, b1, pT);
    }
    {
        dim3 grid(DD / 128, BL / 256);   // (8, 16)
        ffn2_t5<<<grid, 256, GEMM_SMEM>>>(pT, W2, b2, pX3, out);
    }
}